// round 7
// baseline (speedup 1.0000x reference)
#include <cuda_runtime.h>
#include <cuda_bf16.h>
#include <cstdint>

// ---------------------------------------------------------------------------
// KimiDeltaAttention — mma.sync bf16-split GEMMs (fp32-accurate) + fp32 scan
// B=4, T=2048, HID=2048, H=16, DK=DV=128
// compute_103 PTX only (no 'a' features): tensor path = mma.sync m16n8k16 bf16.
// ---------------------------------------------------------------------------

#define Bc 4
#define Tc 2048
#define HIDc 2048
#define Hc 16
#define DKc 128
#define DVc 128
#define Mc (Bc * Tc)            // 8192 rows

typedef unsigned long long ull;
typedef unsigned int u32;

// ------------------------- fp32 scratch (device globals) -------------------
__device__ float g_q   [(size_t)Mc * HIDc];
__device__ float g_k   [(size_t)Mc * HIDc];
__device__ float g_v   [(size_t)Mc * HIDc];
__device__ float g_eg  [(size_t)Mc * HIDc];   // exp(gate)
__device__ float g_sigf[(size_t)Mc * HIDc];   // sigmoid(factor)
__device__ float g_o   [(size_t)Mc * HIDc];
__device__ float g_tmp [(size_t)Mc * 128];    // low-rank intermediate (f path)
__device__ float g_tmp2[(size_t)Mc * 128];    // low-rank intermediate (g path)
__device__ float g_beta[(size_t)Mc * Hc];

#define ID_Q    0
#define ID_K    1
#define ID_V    2
#define ID_EG   3
#define ID_SIGF 4
#define ID_O    5
#define ID_TMP  6
#define ID_TMP2 7
#define ID_BETA 8

__device__ __forceinline__ float* scratch_resolve(int id) {
    switch (id) {
        case ID_Q:    return g_q;
        case ID_K:    return g_k;
        case ID_V:    return g_v;
        case ID_EG:   return g_eg;
        case ID_SIGF: return g_sigf;
        case ID_O:    return g_o;
        case ID_TMP:  return g_tmp;
        case ID_TMP2: return g_tmp2;
        default:      return g_beta;
    }
}

// ------------------------- bf16 split pool ---------------------------------
// every operand is a contiguous [hi block][lo block] pair (lo = hi + blocksz)
constexpr size_t OFF_HB_HI   = 0;
constexpr size_t BS_HB       = (size_t)Mc * HIDc;
constexpr size_t OFF_WQ_HI   = OFF_HB_HI + 2 * BS_HB;      // WQ,WK,WV consecutive
constexpr size_t BS_W        = (size_t)HIDc * HIDc;
constexpr size_t OFF_WO_HI   = OFF_WQ_HI + 6 * BS_W;
constexpr size_t OFF_FW0_HI  = OFF_WO_HI + 2 * BS_W;       // FW0, GW0 consecutive
constexpr size_t BS_W0       = (size_t)128 * HIDc;
constexpr size_t OFF_FW1_HI  = OFF_FW0_HI + 4 * BS_W0;
constexpr size_t BS_W1       = (size_t)HIDc * 128;
constexpr size_t OFF_GW1_HI  = OFF_FW1_HI + 2 * BS_W1;
constexpr size_t OFF_TMP_HI  = OFF_GW1_HI + 2 * BS_W1;
constexpr size_t BS_TMP      = (size_t)Mc * 128;
constexpr size_t OFF_TMP2_HI = OFF_TMP_HI + 2 * BS_TMP;
constexpr size_t OFF_OG_HI   = OFF_TMP2_HI + 2 * BS_TMP;
constexpr size_t BS_OG       = (size_t)Mc * HIDc;
constexpr size_t BF_TOTAL    = OFF_OG_HI + 2 * BS_OG;

__device__ __nv_bfloat16 g_bfpool[BF_TOTAL];

// ------------------------------ f32x2 helpers ------------------------------
__device__ __forceinline__ ull f2pack(float a, float b) {
    ull r; asm("mov.b64 %0, {%1, %2};" : "=l"(r) : "f"(a), "f"(b)); return r;
}
__device__ __forceinline__ float2 f2unpack(ull x) {
    float2 r; asm("mov.b64 {%0, %1}, %2;" : "=f"(r.x), "=f"(r.y) : "l"(x)); return r;
}
__device__ __forceinline__ ull ffma2(ull a, ull b, ull c) {
    ull d; asm("fma.rn.f32x2 %0, %1, %2, %3;" : "=l"(d) : "l"(a), "l"(b), "l"(c)); return d;
}
__device__ __forceinline__ ull fmul2(ull a, ull b) {
    ull d; asm("mul.rn.f32x2 %0, %1, %2;" : "=l"(d) : "l"(a), "l"(b)); return d;
}

// ------------------------------ async copy ---------------------------------
__device__ __forceinline__ void cp16(void* s, const void* g) {
    u32 sa = (u32)__cvta_generic_to_shared(s);
    asm volatile("cp.async.ca.shared.global [%0], [%1], 16;" :: "r"(sa), "l"(g));
}
__device__ __forceinline__ void cp16u(u32 s, const void* g) {
    asm volatile("cp.async.cg.shared.global [%0], [%1], 16;" :: "r"(s), "l"(g));
}
__device__ __forceinline__ void cp4(void* s, const void* g) {
    u32 sa = (u32)__cvta_generic_to_shared(s);
    asm volatile("cp.async.ca.shared.global [%0], [%1], 4;" :: "r"(sa), "l"(g));
}
__device__ __forceinline__ void cp_commit() { asm volatile("cp.async.commit_group;"); }

__device__ __forceinline__ u32 smem_u32(const void* p) {
    return (u32)__cvta_generic_to_shared(p);
}

// ------------------------------ mma helpers --------------------------------
__device__ __forceinline__ void mma16816(float* c, const u32* a, const u32* b) {
    asm volatile(
        "mma.sync.aligned.m16n8k16.row.col.f32.bf16.bf16.f32 "
        "{%0,%1,%2,%3}, {%4,%5,%6,%7}, {%8,%9}, {%0,%1,%2,%3};"
        : "+f"(c[0]), "+f"(c[1]), "+f"(c[2]), "+f"(c[3])
        : "r"(a[0]), "r"(a[1]), "r"(a[2]), "r"(a[3]), "r"(b[0]), "r"(b[1]));
}
__device__ __forceinline__ void ldsm4(u32* r, u32 addr) {
    asm volatile("ldmatrix.sync.aligned.m8n8.x4.shared.b16 {%0,%1,%2,%3}, [%4];"
        : "=r"(r[0]), "=r"(r[1]), "=r"(r[2]), "=r"(r[3]) : "r"(addr));
}

// ------------------------------ split kernel -------------------------------
__global__ __launch_bounds__(256) void split_kernel(
    const float* __restrict__ ext, int srcId, size_t off_hi, size_t blocksz)
{
    const float* src = (srcId >= 0) ? scratch_resolve(srcId) : ext;
    size_t i = ((size_t)blockIdx.x * 256 + threadIdx.x) * 4;
    float4 x = *(const float4*)(src + i);
    __nv_bfloat16 h0 = __float2bfloat16(x.x), h1 = __float2bfloat16(x.y);
    __nv_bfloat16 h2 = __float2bfloat16(x.z), h3 = __float2bfloat16(x.w);
    __nv_bfloat16 l0 = __float2bfloat16(x.x - __bfloat162float(h0));
    __nv_bfloat16 l1 = __float2bfloat16(x.y - __bfloat162float(h1));
    __nv_bfloat16 l2 = __float2bfloat16(x.z - __bfloat162float(h2));
    __nv_bfloat16 l3 = __float2bfloat16(x.w - __bfloat162float(h3));
    uint2 ph, pl;
    ph.x = (u32)__bfloat16_as_ushort(h0) | ((u32)__bfloat16_as_ushort(h1) << 16);
    ph.y = (u32)__bfloat16_as_ushort(h2) | ((u32)__bfloat16_as_ushort(h3) << 16);
    pl.x = (u32)__bfloat16_as_ushort(l0) | ((u32)__bfloat16_as_ushort(l1) << 16);
    pl.y = (u32)__bfloat16_as_ushort(l2) | ((u32)__bfloat16_as_ushort(l3) << 16);
    *(uint2*)(g_bfpool + off_hi + i) = ph;
    *(uint2*)(g_bfpool + off_hi + blocksz + i) = pl;
}

// ------------------------- mma.sync split-bf16 GEMM ------------------------
// C[M,N] = act( A[M,K] @ W[N,K]^T ):  D += Ahi*Whi + Ahi*Wlo + Alo*Whi
// CTA 128x128, 256 thr (8 warps 2x4; warp tile 64x32), BK=32, 4-stage cp.async
// pipeline (prefetch distance 2, single barrier/chunk), XOR-swizzled smem.
// blockIdx.z selects operand set: W block z (stride 2*w_bs), C id Cid+z.
// ACT: 0 none | 1 silu | 2 kda-gate->exp | 3 sigmoid(x+aux1[n])
constexpr int BKg         = 32;
constexpr int TILE_BYTES  = 128 * BKg * 2;     // 8 KB
constexpr int STAGE_BYTES = 4 * TILE_BYTES;    // 32 KB
constexpr int GSMEM       = 4 * STAGE_BYTES;   // 128 KB

template <int ACT>
__global__ __launch_bounds__(256) void mma_gemm(
    size_t a_hi, size_t a_bs, size_t w_hi, size_t w_bs,
    float* __restrict__ Cext, int Cid, int Ntot, int Ktot,
    const float* __restrict__ aux1, const float* __restrict__ aux2)
{
    extern __shared__ char dsm[];
    const u32 sb = smem_u32(dsm);
    const int tid = threadIdx.x, lane = tid & 31, wid = tid >> 5;
    const int warp_m = wid & 1, warp_n = wid >> 1;    // 2 x 4 warp grid
    const int bm = blockIdx.y, bn = blockIdx.x, bz = blockIdx.z;

    const size_t whi = w_hi + (size_t)bz * 2 * w_bs;
    const __nv_bfloat16* srcs[4] = {
        g_bfpool + a_hi +        (size_t)bm * 128 * Ktot,
        g_bfpool + a_hi + a_bs + (size_t)bm * 128 * Ktot,
        g_bfpool + whi +         (size_t)bn * 128 * Ktot,
        g_bfpool + whi + w_bs +  (size_t)bn * 128 * Ktot };

    float acc[4][4][4];
#pragma unroll
    for (int i = 0; i < 4; i++)
#pragma unroll
        for (int j = 0; j < 4; j++)
#pragma unroll
            for (int e = 0; e < 4; e++) acc[i][j][e] = 0.f;

    const int NC = Ktot / BKg;
    const int jq = lane >> 3, rq = lane & 7;
    const int jlow = jq & 1, jhi = jq >> 1;

    auto load_stage = [&](int stage, int c) {
        u32 base = sb + (u32)stage * STAGE_BYTES;
#pragma unroll
        for (int t = 0; t < 4; t++) {
            const __nv_bfloat16* src = srcs[t] + (size_t)c * BKg;
            u32 tb = base + (u32)t * TILE_BYTES;
#pragma unroll
            for (int i = 0; i < 2; i++) {
                int idx = tid + i * 256;                 // 0..511
                u32 row = (u32)(idx >> 2), g = (u32)(idx & 3);
                u32 so = tb + row * 64u + ((g ^ (row & 3u)) * 16u);
                cp16u(so, (const char*)(src + (size_t)row * Ktot) + g * 16);
            }
        }
    };

    load_stage(0, 0); cp_commit();
    load_stage(1, 1); cp_commit();

    for (int c = 0; c < NC; c++) {
        if (c + 2 < NC) {
            load_stage((c + 2) & 3, c + 2); cp_commit();
            asm volatile("cp.async.wait_group 2;" ::: "memory");
        } else {
            asm volatile("cp.async.wait_group 0;" ::: "memory");
        }
        __syncthreads();

        const u32 base = sb + (u32)(c & 3) * STAGE_BYTES;
        const u32 ah = base, al = base + TILE_BYTES;
        const u32 wh = base + 2 * TILE_BYTES, wl = base + 3 * TILE_BYTES;

#pragma unroll
        for (int ks = 0; ks < 2; ks++) {
            const u32 g = (u32)(ks * 2 + jhi);
            u32 a_hi_f[4][4], a_lo_f[4][4];
#pragma unroll
            for (int mi = 0; mi < 4; mi++) {
                u32 row = (u32)(warp_m * 64 + mi * 16 + jlow * 8 + rq);
                u32 off = row * 64u + ((g ^ (row & 3u)) * 16u);
                ldsm4(a_hi_f[mi], ah + off);
                ldsm4(a_lo_f[mi], al + off);
            }
            u32 b_hi_f[4][2], b_lo_f[4][2];
#pragma unroll
            for (int pi = 0; pi < 2; pi++) {
                u32 row = (u32)(warp_n * 32 + pi * 16 + jlow * 8 + rq);
                u32 off = row * 64u + ((g ^ (row & 3u)) * 16u);
                u32 t0[4], t1[4];
                ldsm4(t0, wh + off);
                ldsm4(t1, wl + off);
                b_hi_f[2*pi][0] = t0[0]; b_hi_f[2*pi][1] = t0[2];
                b_hi_f[2*pi+1][0] = t0[1]; b_hi_f[2*pi+1][1] = t0[3];
                b_lo_f[2*pi][0] = t1[0]; b_lo_f[2*pi][1] = t1[2];
                b_lo_f[2*pi+1][0] = t1[1]; b_lo_f[2*pi+1][1] = t1[3];
            }
#pragma unroll
            for (int mi = 0; mi < 4; mi++)
#pragma unroll
                for (int ni = 0; ni < 4; ni++) {
                    mma16816(acc[mi][ni], a_hi_f[mi], b_hi_f[ni]);
                    mma16816(acc[mi][ni], a_hi_f[mi], b_lo_f[ni]);
                    mma16816(acc[mi][ni], a_lo_f[mi], b_hi_f[ni]);
                }
        }
        // no end barrier: prefetch distance 2 over 4 stages keeps writes
        // 3 stages away from any in-flight readers.
    }

    float* C = (Cid >= 0) ? scratch_resolve(Cid + bz) : Cext;
    const int qrow = lane >> 2, qcol = (lane & 3) * 2;
    const int n_warp0 = bn * 128 + warp_n * 32;
#pragma unroll
    for (int mi = 0; mi < 4; mi++) {
#pragma unroll
        for (int half = 0; half < 2; half++) {
            const int m = bm * 128 + warp_m * 64 + mi * 16 + half * 8 + qrow;
            float* crow = C + (size_t)m * Ntot + n_warp0;
#pragma unroll
            for (int ni = 0; ni < 4; ni++) {
                float x0 = acc[mi][ni][half * 2];
                float x1 = acc[mi][ni][half * 2 + 1];
                const int n = n_warp0 + ni * 8 + qcol;
                if (ACT == 1) {
                    x0 = x0 / (1.0f + expf(-x0));
                    x1 = x1 / (1.0f + expf(-x1));
                } else if (ACT == 2) {
                    float a0 = expf(aux1[n >> 7]);
                    float a1 = expf(aux1[(n + 1) >> 7]);
                    float s0 = x0 + aux2[n], s1 = x1 + aux2[n + 1];
                    s0 = (s0 > 20.0f) ? s0 : log1pf(expf(s0));
                    s1 = (s1 > 20.0f) ? s1 : log1pf(expf(s1));
                    x0 = expf(-a0 * s0); x1 = expf(-a1 * s1);
                } else if (ACT == 3) {
                    x0 = 1.0f / (1.0f + expf(-(x0 + aux1[n])));
                    x1 = 1.0f / (1.0f + expf(-(x1 + aux1[n + 1])));
                }
                float2 o2; o2.x = x0; o2.y = x1;
                *(float2*)(crow + ni * 8 + qcol) = o2;
            }
        }
    }
}

// --------------------------- beta = sigmoid(h @ b_w^T) ---------------------
__global__ __launch_bounds__(512) void beta_kernel(
    const float* __restrict__ H, const float* __restrict__ BW)
{
    float* BETA = scratch_resolve(ID_BETA);
    const int m = blockIdx.x;
    const int w = threadIdx.x >> 5, lane = threadIdx.x & 31;
    const float4* hr = (const float4*)(H + (size_t)m * HIDc);
    const float4* br = (const float4*)(BW + (size_t)w * HIDc);
    float s = 0.f;
#pragma unroll 4
    for (int i = lane; i < HIDc / 4; i += 32) {
        float4 a = hr[i], b = br[i];
        s += a.x * b.x + a.y * b.y + a.z * b.z + a.w * b.w;
    }
#pragma unroll
    for (int off = 16; off > 0; off >>= 1)
        s += __shfl_xor_sync(0xffffffffu, s, off);
    if (lane == 0) BETA[(size_t)m * Hc + w] = 1.0f / (1.0f + expf(-s));
}

// ------------------- per-head L2 norm (in place, q & k merged) -------------
__global__ __launch_bounds__(128) void l2norm_kernel()
{
    const int z = blockIdx.z;
    float* X = scratch_resolve(z ? ID_K : ID_Q);
    const float scale = z ? 1.0f : 0.08838834764831845f;
    const int h = blockIdx.x, m = blockIdx.y;
    const int v = threadIdx.x;
    const size_t off = (size_t)m * HIDc + (size_t)h * DKc + v;
    float x = X[off];
    float s = x * x;
#pragma unroll
    for (int o = 16; o > 0; o >>= 1) s += __shfl_xor_sync(0xffffffffu, s, o);
    __shared__ float red[4];
    if ((v & 31) == 0) red[v >> 5] = s;
    __syncthreads();
    float tot = red[0] + red[1] + red[2] + red[3];
    X[off] = x * rsqrtf(tot + 1e-6f) * scale;
}

// ---------- gated RMS norm: og = rms(o)*w*sigf, emitted as bf16 hi/lo ------
__global__ __launch_bounds__(128) void gate_kernel(const float* __restrict__ NW)
{
    const float* O    = scratch_resolve(ID_O);
    const float* SIGF = scratch_resolve(ID_SIGF);
    const int h = blockIdx.x, m = blockIdx.y;
    const int v = threadIdx.x;
    const size_t off = (size_t)m * HIDc + (size_t)h * DVc + v;
    float x = O[off];
    float s = x * x;
#pragma unroll
    for (int o = 16; o > 0; o >>= 1) s += __shfl_xor_sync(0xffffffffu, s, o);
    __shared__ float red[4];
    if ((v & 31) == 0) red[v >> 5] = s;
    __syncthreads();
    float tot = red[0] + red[1] + red[2] + red[3];
    float r = rsqrtf(tot * (1.0f / DVc) + 1e-5f);
    float y = x * r * NW[v] * SIGF[off];
    __nv_bfloat16 hi = __float2bfloat16(y);
    __nv_bfloat16 lo = __float2bfloat16(y - __bfloat162float(hi));
    g_bfpool[OFF_OG_HI + off] = hi;
    g_bfpool[OFF_OG_HI + BS_OG + off] = lo;
}

// ------------------------------ recurrent scan -----------------------------
// grid (2, H, B); 256 threads. CTA owns 64 v-cols; 4 threads split the 128-k
// dim (kq = tid&3, 32 k each). 4 smem stages, prefetch distance 2 -> single
// barrier per step. Rows skewed +4 floats per 32-block so the 4 k-quarters
// hit distinct banks (unskewed they are 128B apart = same bank).
#define SROW 144
#define SKW(i) ((i) + ((((u32)(i)) >> 5) << 2))

__global__ __launch_bounds__(256) void scan_kernel(
    const float* __restrict__ S0,
    float* __restrict__ Sout, int writeS)
{
    const float* Q    = scratch_resolve(ID_Q);
    const float* K    = scratch_resolve(ID_K);
    const float* V    = scratch_resolve(ID_V);
    const float* EG   = scratch_resolve(ID_EG);
    const float* BETA = scratch_resolve(ID_BETA);
    float*       O    = scratch_resolve(ID_O);

    const int vh = blockIdx.x, h = blockIdx.y, b = blockIdx.z;
    const int tid = threadIdx.x;
    const int vloc = tid >> 2, kq = tid & 3;
    const int v = vh * 64 + vloc;
    const int ks = kq * 32;

    __shared__ float sbuf[4][4][SROW];   // [stage][k,q,v,eg][128 skewed]
    __shared__ float sbeta[4];

    const size_t rowbase = (size_t)b * Tc * HIDc + (size_t)h * DKc;

    // state S[k in ks..ks+31][v], 16 f32x2 pairs
    ull S[16];
    {
        const float* s0p = S0 + (((size_t)(b * Hc + h) * DKc + ks) * DVc + v);
#pragma unroll
        for (int j2 = 0; j2 < 16; j2++)
            S[j2] = f2pack(s0p[(size_t)(2 * j2) * DVc], s0p[(size_t)(2 * j2 + 1) * DVc]);
    }

    const int grp = tid >> 6, idx = tid & 63;
    const float* srcs[4] = {K, Q, V, EG};

    // prologue: prefetch t=0,1
#pragma unroll
    for (int t = 0; t < 2; t++) {
        if (idx < 32)
            cp16(&sbuf[t][grp][idx * 4 + ((idx >> 3) << 2)],
                 srcs[grp] + rowbase + (size_t)t * HIDc + idx * 4);
        if (tid == 0) cp4(&sbeta[t], BETA + ((size_t)(b * Tc + t)) * Hc + h);
        cp_commit();
    }

    for (int t = 0; t < Tc; t++) {
        if (t + 2 < Tc) {
            const int st = (t + 2) & 3;
            if (idx < 32)
                cp16(&sbuf[st][grp][idx * 4 + ((idx >> 3) << 2)],
                     srcs[grp] + rowbase + (size_t)(t + 2) * HIDc + idx * 4);
            if (tid == 0) cp4(&sbeta[st], BETA + ((size_t)(b * Tc + t + 2)) * Hc + h);
            cp_commit();
            asm volatile("cp.async.wait_group 2;" ::: "memory");
        } else {
            asm volatile("cp.async.wait_group 0;" ::: "memory");
        }
        __syncthreads();

        const int cb = t & 3;
        const float beta = sbeta[cb];
        const float vv = sbuf[cb][2][SKW(v)];
        const int kb = ks + kq * 4;        // skewed base for this k-quarter

        ull k2[16];
        ull kv2 = 0ull;
#pragma unroll
        for (int j2 = 0; j2 < 16; j2++) {
            k2[j2]  = *(const ull*)&sbuf[cb][0][kb + 2 * j2];
            ull eg2 = *(const ull*)&sbuf[cb][3][kb + 2 * j2];
            S[j2] = fmul2(S[j2], eg2);
            kv2 = ffma2(k2[j2], S[j2], kv2);
        }
        float2 kvp = f2unpack(kv2);
        float kv = kvp.x + kvp.y;
        kv += __shfl_xor_sync(0xffffffffu, kv, 1);
        kv += __shfl_xor_sync(0xffffffffu, kv, 2);

        const float delta = (vv - kv) * beta;
        const ull d2 = f2pack(delta, delta);

        ull o2 = 0ull;
#pragma unroll
        for (int j2 = 0; j2 < 16; j2++) {
            S[j2] = ffma2(k2[j2], d2, S[j2]);
            ull q2 = *(const ull*)&sbuf[cb][1][kb + 2 * j2];
            o2 = ffma2(q2, S[j2], o2);
        }
        float2 op = f2unpack(o2);
        float o = op.x + op.y;
        o += __shfl_xor_sync(0xffffffffu, o, 1);
        o += __shfl_xor_sync(0xffffffffu, o, 2);
        if (kq == 0)
            O[rowbase + (size_t)t * HIDc + v] = o;
        // no end barrier: prefetch targets stage (t+2)&3 == (t-2)&3, whose
        // readers completed before barrier t-1.
    }

    if (writeS) {
        float* sp = Sout + (((size_t)(b * Hc + h) * DKc + ks) * DVc + v);
#pragma unroll
        for (int j2 = 0; j2 < 16; j2++) {
            float2 c = f2unpack(S[j2]);
            sp[(size_t)(2 * j2) * DVc]     = c.x;
            sp[(size_t)(2 * j2 + 1) * DVc] = c.y;
        }
    }
}

// ------------------------------ host launcher ------------------------------
extern "C" void kernel_launch(void* const* d_in, const int* in_sizes, int n_in,
                              void* d_out, int out_size)
{
    const float* h      = (const float*)d_in[0];
    const float* S0     = (const float*)d_in[1];
    const float* q_w    = (const float*)d_in[2];
    const float* k_w    = (const float*)d_in[3];
    const float* v_w    = (const float*)d_in[4];
    const float* f_w0   = (const float*)d_in[5];
    const float* f_w1   = (const float*)d_in[6];
    const float* b_w    = (const float*)d_in[7];
    const float* A_log  = (const float*)d_in[8];
    const float* dt_b   = (const float*)d_in[9];
    const float* g_w0   = (const float*)d_in[10];
    const float* g_w1   = (const float*)d_in[11];
    const float* g_b1   = (const float*)d_in[12];
    const float* o_nw   = (const float*)d_in[13];
    const float* o_w    = (const float*)d_in[14];
    float* out = (float*)d_out;

    cudaFuncSetAttribute(mma_gemm<0>, cudaFuncAttributeMaxDynamicSharedMemorySize, GSMEM);
    cudaFuncSetAttribute(mma_gemm<1>, cudaFuncAttributeMaxDynamicSharedMemorySize, GSMEM);
    cudaFuncSetAttribute(mma_gemm<2>, cudaFuncAttributeMaxDynamicSharedMemorySize, GSMEM);
    cudaFuncSetAttribute(mma_gemm<3>, cudaFuncAttributeMaxDynamicSharedMemorySize, GSMEM);

    // ---- split inputs into bf16 hi/lo ----
    split_kernel<<<(Mc * HIDc) / 1024, 256>>>(h,    -1, OFF_HB_HI,  BS_HB);
    split_kernel<<<(HIDc * HIDc) / 1024, 256>>>(q_w, -1, OFF_WQ_HI,            BS_W);
    split_kernel<<<(HIDc * HIDc) / 1024, 256>>>(k_w, -1, OFF_WQ_HI + 2 * BS_W, BS_W);
    split_kernel<<<(HIDc * HIDc) / 1024, 256>>>(v_w, -1, OFF_WQ_HI + 4 * BS_W, BS_W);
    split_kernel<<<(HIDc * HIDc) / 1024, 256>>>(o_w, -1, OFF_WO_HI,  BS_W);
    split_kernel<<<(128 * HIDc) / 1024, 256>>>(f_w0, -1, OFF_FW0_HI,            BS_W0);
    split_kernel<<<(128 * HIDc) / 1024, 256>>>(g_w0, -1, OFF_FW0_HI + 2 * BS_W0, BS_W0);
    split_kernel<<<(HIDc * 128) / 1024, 256>>>(f_w1, -1, OFF_FW1_HI, BS_W1);
    split_kernel<<<(HIDc * 128) / 1024, 256>>>(g_w1, -1, OFF_GW1_HI, BS_W1);

    // ---- q,k,v projections in ONE launch (z selects weight; silu fused) ----
    mma_gemm<1><<<dim3(16, 64, 3), 256, GSMEM>>>(OFF_HB_HI, BS_HB, OFF_WQ_HI, BS_W,
                                                 nullptr, ID_Q, HIDc, HIDc, nullptr, nullptr);

    // ---- both skinny K=2048->N=128 GEMMs in ONE launch (f path & g path) ----
    mma_gemm<0><<<dim3(1, 64, 2), 256, GSMEM>>>(OFF_HB_HI, BS_HB, OFF_FW0_HI, BS_W0,
                                                nullptr, ID_TMP, 128, HIDc, nullptr, nullptr);
    split_kernel<<<(Mc * 128) / 1024, 256>>>(nullptr, ID_TMP,  OFF_TMP_HI,  BS_TMP);
    split_kernel<<<(Mc * 128) / 1024, 256>>>(nullptr, ID_TMP2, OFF_TMP2_HI, BS_TMP);

    // ---- eg = exp(-exp(A_log)*softplus(tmp@f_w1^T + dt_bias)) ----
    mma_gemm<2><<<dim3(16, 64, 1), 256, GSMEM>>>(OFF_TMP_HI, BS_TMP, OFF_FW1_HI, BS_W1,
                                                 nullptr, ID_EG, HIDc, 128, A_log, dt_b);
    // ---- sigf = sigmoid(tmp2@g_w1^T + g_b1) ----
    mma_gemm<3><<<dim3(16, 64, 1), 256, GSMEM>>>(OFF_TMP2_HI, BS_TMP, OFF_GW1_HI, BS_W1,
                                                 nullptr, ID_SIGF, HIDc, 128, g_b1, nullptr);

    // ---- beta + merged l2 norms ----
    beta_kernel<<<Mc, 512>>>(h, b_w);
    l2norm_kernel<<<dim3(Hc, Mc, 2), 128>>>();

    // ---- recurrent scan ----
    const size_t out_elems = (size_t)Mc * HIDc;                 // 16,777,216
    const size_t s_elems   = (size_t)Bc * Hc * DKc * DVc;       //  1,048,576
    const int writeS = ((size_t)out_size >= out_elems + s_elems) ? 1 : 0;
    scan_kernel<<<dim3(2, Hc, Bc), 256>>>(S0, out + out_elems, writeS);

    // ---- gated rms norm (emits bf16 hi/lo) + final projection ----
    gate_kernel<<<dim3(Hc, Mc), 128>>>(o_nw);
    mma_gemm<0><<<dim3(16, 64, 1), 256, GSMEM>>>(OFF_OG_HI, BS_OG, OFF_WO_HI, BS_W,
                                                 out, -1, HIDc, HIDc, nullptr, nullptr);
}

// round 9
// speedup vs baseline: 1.2478x; 1.2478x over previous
#include <cuda_runtime.h>
#include <cuda_fp16.h>
#include <cuda_bf16.h>
#include <cstdint>

// ---------------------------------------------------------------------------
// KimiDeltaAttention — mma.sync fp16 GEMMs (A hi/lo split, W fp16; 2 MMAs per
// product, fp32 accum) + fp32 scan with multi-accumulator chains.
// B=4, T=2048, HID=2048, H=16, DK=DV=128
// compute_103 PTX only (no 'a' features): tensor path = mma.sync m16n8k16 f16.
// ---------------------------------------------------------------------------

#define Bc 4
#define Tc 2048
#define HIDc 2048
#define Hc 16
#define DKc 128
#define DVc 128
#define Mc (Bc * Tc)            // 8192 rows

typedef unsigned long long ull;
typedef unsigned int u32;

// ------------------------- fp32 scratch (device globals) -------------------
__device__ float g_q   [(size_t)Mc * HIDc];
__device__ float g_k   [(size_t)Mc * HIDc];
__device__ float g_v   [(size_t)Mc * HIDc];
__device__ float g_eg  [(size_t)Mc * HIDc];   // exp(gate)
__device__ float g_sigf[(size_t)Mc * HIDc];   // sigmoid(factor)
__device__ float g_o   [(size_t)Mc * HIDc];
__device__ float g_tmp [(size_t)Mc * 128];    // low-rank intermediate
__device__ float g_beta[(size_t)Mc * Hc];

#define ID_Q    0
#define ID_K    1
#define ID_V    2
#define ID_EG   3
#define ID_SIGF 4
#define ID_O    5
#define ID_TMP  6
#define ID_BETA 7

__device__ __forceinline__ float* scratch_resolve(int id) {
    switch (id) {
        case ID_Q:    return g_q;
        case ID_K:    return g_k;
        case ID_V:    return g_v;
        case ID_EG:   return g_eg;
        case ID_SIGF: return g_sigf;
        case ID_O:    return g_o;
        case ID_TMP:  return g_tmp;
        default:      return g_beta;
    }
}

// ------------------------- fp16 split pool ---------------------------------
constexpr size_t OFF_HB_HI  = 0;
constexpr size_t OFF_HB_LO  = OFF_HB_HI  + (size_t)Mc * HIDc;
constexpr size_t OFF_WQ_HI  = OFF_HB_LO  + (size_t)Mc * HIDc;
constexpr size_t OFF_WQ_LO  = OFF_WQ_HI  + (size_t)HIDc * HIDc;
constexpr size_t OFF_WK_HI  = OFF_WQ_LO  + (size_t)HIDc * HIDc;
constexpr size_t OFF_WK_LO  = OFF_WK_HI  + (size_t)HIDc * HIDc;
constexpr size_t OFF_WV_HI  = OFF_WK_LO  + (size_t)HIDc * HIDc;
constexpr size_t OFF_WV_LO  = OFF_WV_HI  + (size_t)HIDc * HIDc;
constexpr size_t OFF_WO_HI  = OFF_WV_LO  + (size_t)HIDc * HIDc;
constexpr size_t OFF_WO_LO  = OFF_WO_HI  + (size_t)HIDc * HIDc;
constexpr size_t OFF_FW0_HI = OFF_WO_LO  + (size_t)HIDc * HIDc;
constexpr size_t OFF_FW0_LO = OFF_FW0_HI + (size_t)128 * HIDc;
constexpr size_t OFF_GW0_HI = OFF_FW0_LO + (size_t)128 * HIDc;
constexpr size_t OFF_GW0_LO = OFF_GW0_HI + (size_t)128 * HIDc;
constexpr size_t OFF_FW1_HI = OFF_GW0_LO + (size_t)128 * HIDc;
constexpr size_t OFF_FW1_LO = OFF_FW1_HI + (size_t)HIDc * 128;
constexpr size_t OFF_GW1_HI = OFF_FW1_LO + (size_t)HIDc * 128;
constexpr size_t OFF_GW1_LO = OFF_GW1_HI + (size_t)HIDc * 128;
constexpr size_t OFF_TMP_HI = OFF_GW1_LO + (size_t)HIDc * 128;
constexpr size_t OFF_TMP_LO = OFF_TMP_HI + (size_t)Mc * 128;
constexpr size_t OFF_OG_HI  = OFF_TMP_LO + (size_t)Mc * 128;
constexpr size_t OFF_OG_LO  = OFF_OG_HI  + (size_t)Mc * HIDc;
constexpr size_t HF_TOTAL   = OFF_OG_LO  + (size_t)Mc * HIDc;

__device__ __half g_hfpool[HF_TOTAL];

// ------------------------------ f32x2 helpers ------------------------------
__device__ __forceinline__ ull f2pack(float a, float b) {
    ull r; asm("mov.b64 %0, {%1, %2};" : "=l"(r) : "f"(a), "f"(b)); return r;
}
__device__ __forceinline__ float2 f2unpack(ull x) {
    float2 r; asm("mov.b64 {%0, %1}, %2;" : "=f"(r.x), "=f"(r.y) : "l"(x)); return r;
}
__device__ __forceinline__ ull ffma2(ull a, ull b, ull c) {
    ull d; asm("fma.rn.f32x2 %0, %1, %2, %3;" : "=l"(d) : "l"(a), "l"(b), "l"(c)); return d;
}
__device__ __forceinline__ ull fmul2(ull a, ull b) {
    ull d; asm("mul.rn.f32x2 %0, %1, %2;" : "=l"(d) : "l"(a), "l"(b)); return d;
}
__device__ __forceinline__ ull fadd2(ull a, ull b) {
    ull d; asm("add.rn.f32x2 %0, %1, %2;" : "=l"(d) : "l"(a), "l"(b)); return d;
}

// ------------------------------ async copy ---------------------------------
__device__ __forceinline__ void cp16(void* s, const void* g) {
    u32 sa = (u32)__cvta_generic_to_shared(s);
    asm volatile("cp.async.ca.shared.global [%0], [%1], 16;" :: "r"(sa), "l"(g));
}
__device__ __forceinline__ void cp16u(u32 s, const void* g) {
    asm volatile("cp.async.cg.shared.global [%0], [%1], 16;" :: "r"(s), "l"(g));
}
__device__ __forceinline__ void cp4(void* s, const void* g) {
    u32 sa = (u32)__cvta_generic_to_shared(s);
    asm volatile("cp.async.ca.shared.global [%0], [%1], 4;" :: "r"(sa), "l"(g));
}
__device__ __forceinline__ void cp_commit() { asm volatile("cp.async.commit_group;"); }
__device__ __forceinline__ void cp_wait2()  { asm volatile("cp.async.wait_group 2;"); }

__device__ __forceinline__ u32 smem_u32(const void* p) {
    return (u32)__cvta_generic_to_shared(p);
}

// ------------------------------ mma helpers --------------------------------
__device__ __forceinline__ void mma16816(float* c, const u32* a, const u32* b) {
    asm volatile(
        "mma.sync.aligned.m16n8k16.row.col.f32.f16.f16.f32 "
        "{%0,%1,%2,%3}, {%4,%5,%6,%7}, {%8,%9}, {%0,%1,%2,%3};"
        : "+f"(c[0]), "+f"(c[1]), "+f"(c[2]), "+f"(c[3])
        : "r"(a[0]), "r"(a[1]), "r"(a[2]), "r"(a[3]), "r"(b[0]), "r"(b[1]));
}
__device__ __forceinline__ void ldsm4(u32* r, u32 addr) {
    asm volatile("ldmatrix.sync.aligned.m8n8.x4.shared.b16 {%0,%1,%2,%3}, [%4];"
        : "=r"(r[0]), "=r"(r[1]), "=r"(r[2]), "=r"(r[3]) : "r"(addr));
}

// ------------------------------ split kernel -------------------------------
// x -> hi = fp16(x), lo = fp16(x - hi). 4 elems/thread, vectorized.
__global__ __launch_bounds__(256) void split_kernel(
    const float* __restrict__ ext, int srcId, size_t off_hi, size_t off_lo)
{
    const float* src = (srcId >= 0) ? scratch_resolve(srcId) : ext;
    size_t i = ((size_t)blockIdx.x * 256 + threadIdx.x) * 4;
    float4 x = *(const float4*)(src + i);
    __half h0 = __float2half_rn(x.x), h1 = __float2half_rn(x.y);
    __half h2 = __float2half_rn(x.z), h3 = __float2half_rn(x.w);
    __half l0 = __float2half_rn(x.x - __half2float(h0));
    __half l1 = __float2half_rn(x.y - __half2float(h1));
    __half l2 = __float2half_rn(x.z - __half2float(h2));
    __half l3 = __float2half_rn(x.w - __half2float(h3));
    uint2 ph, pl;
    ph.x = (u32)__half_as_ushort(h0) | ((u32)__half_as_ushort(h1) << 16);
    ph.y = (u32)__half_as_ushort(h2) | ((u32)__half_as_ushort(h3) << 16);
    pl.x = (u32)__half_as_ushort(l0) | ((u32)__half_as_ushort(l1) << 16);
    pl.y = (u32)__half_as_ushort(l2) | ((u32)__half_as_ushort(l3) << 16);
    *(uint2*)(g_hfpool + off_hi + i) = ph;
    *(uint2*)(g_hfpool + off_lo + i) = pl;
}

// ------------------------- mma.sync fp16 GEMM ------------------------------
// C[M,N] = act( A[M,K] @ W[N,K]^T ), A split hi/lo (error-free), W fp16-hi:
//   D += Ahi*Whi + Alo*Whi   (fp32 accumulators; rel err ~1.4e-4)
// CTA tile 128x128, 256 thr (8 warps, 2x4; warp tile 64x32), BK=32, 2-stage
// cp.async pipeline, XOR-swizzled smem, ldmatrix fragment loads.
// ACT: 0 none | 1 silu | 2 kda-gate->exp | 3 sigmoid(x+aux1[n])
constexpr int BKg         = 32;
constexpr int TILE_BYTES  = 128 * BKg * 2;     // 8 KB
constexpr int STAGE_BYTES = 3 * TILE_BYTES;    // 24 KB (Ahi, Alo, Whi)
constexpr int GSMEM       = 2 * STAGE_BYTES;   // 48 KB

template <int ACT>
__global__ __launch_bounds__(256) void mma_gemm(
    size_t a_hi, size_t a_lo, size_t w_hi,
    float* __restrict__ Cext, int Cid, int Ntot, int Ktot,
    const float* __restrict__ aux1, const float* __restrict__ aux2)
{
    extern __shared__ char dsm[];
    const u32 sb = smem_u32(dsm);
    const int tid = threadIdx.x, lane = tid & 31, wid = tid >> 5;
    const int warp_m = wid & 1, warp_n = wid >> 1;    // 2 x 4 warp grid
    const int bm = blockIdx.y, bn = blockIdx.x;

    const __half* srcs[3] = {
        g_hfpool + a_hi + (size_t)bm * 128 * Ktot,
        g_hfpool + a_lo + (size_t)bm * 128 * Ktot,
        g_hfpool + w_hi + (size_t)bn * 128 * Ktot };

    float acc[4][4][4];
#pragma unroll
    for (int i = 0; i < 4; i++)
#pragma unroll
        for (int j = 0; j < 4; j++)
#pragma unroll
            for (int e = 0; e < 4; e++) acc[i][j][e] = 0.f;

    const int NC = Ktot / BKg;
    const int jq = lane >> 3, rq = lane & 7;
    const int jlow = jq & 1, jhi = jq >> 1;

    // --- stage loader: 3 tiles x 128 rows x 4 x 16B groups, swizzled
    auto load_stage = [&](int stage, int c) {
        u32 base = sb + (u32)stage * STAGE_BYTES;
#pragma unroll
        for (int t = 0; t < 3; t++) {
            const __half* src = srcs[t] + (size_t)c * BKg;
            u32 tb = base + (u32)t * TILE_BYTES;
#pragma unroll
            for (int i = 0; i < 2; i++) {
                int idx = tid + i * 256;                 // 0..511
                u32 row = (u32)(idx >> 2), g = (u32)(idx & 3);
                u32 so = tb + row * 64u + ((g ^ (row & 3u)) * 16u);
                cp16u(so, (const char*)(src + (size_t)row * Ktot) + g * 16);
            }
        }
    };

    load_stage(0, 0); cp_commit();

    for (int c = 0; c < NC; c++) {
        if (c + 1 < NC) {
            load_stage((c + 1) & 1, c + 1); cp_commit();
            asm volatile("cp.async.wait_group 1;" ::: "memory");
        } else {
            asm volatile("cp.async.wait_group 0;" ::: "memory");
        }
        __syncthreads();

        const u32 base = sb + (u32)(c & 1) * STAGE_BYTES;
        const u32 ah = base, al = base + TILE_BYTES;
        const u32 wh = base + 2 * TILE_BYTES;

#pragma unroll
        for (int ks = 0; ks < 2; ks++) {
            const u32 g = (u32)(ks * 2 + jhi);
            u32 a_hi_f[4][4], a_lo_f[4][4];
#pragma unroll
            for (int mi = 0; mi < 4; mi++) {
                u32 row = (u32)(warp_m * 64 + mi * 16 + jlow * 8 + rq);
                u32 off = row * 64u + ((g ^ (row & 3u)) * 16u);
                ldsm4(a_hi_f[mi], ah + off);
                ldsm4(a_lo_f[mi], al + off);
            }
            u32 b_hi_f[4][2];
#pragma unroll
            for (int pi = 0; pi < 2; pi++) {
                u32 row = (u32)(warp_n * 32 + pi * 16 + jlow * 8 + rq);
                u32 off = row * 64u + ((g ^ (row & 3u)) * 16u);
                u32 t0[4];
                ldsm4(t0, wh + off);
                b_hi_f[2*pi][0] = t0[0]; b_hi_f[2*pi][1] = t0[2];
                b_hi_f[2*pi+1][0] = t0[1]; b_hi_f[2*pi+1][1] = t0[3];
            }
#pragma unroll
            for (int mi = 0; mi < 4; mi++)
#pragma unroll
                for (int ni = 0; ni < 4; ni++) {
                    mma16816(acc[mi][ni], a_hi_f[mi], b_hi_f[ni]);
                    mma16816(acc[mi][ni], a_lo_f[mi], b_hi_f[ni]);
                }
        }
        __syncthreads();
    }

    // epilogue
    float* C = (Cid >= 0) ? scratch_resolve(Cid) : Cext;
    const int qrow = lane >> 2, qcol = (lane & 3) * 2;
    const int n_warp0 = bn * 128 + warp_n * 32;
#pragma unroll
    for (int mi = 0; mi < 4; mi++) {
#pragma unroll
        for (int half = 0; half < 2; half++) {
            const int m = bm * 128 + warp_m * 64 + mi * 16 + half * 8 + qrow;
            float* crow = C + (size_t)m * Ntot + n_warp0;
#pragma unroll
            for (int ni = 0; ni < 4; ni++) {
                float x0 = acc[mi][ni][half * 2];
                float x1 = acc[mi][ni][half * 2 + 1];
                const int n = n_warp0 + ni * 8 + qcol;
                if (ACT == 1) {
                    x0 = x0 / (1.0f + expf(-x0));
                    x1 = x1 / (1.0f + expf(-x1));
                } else if (ACT == 2) {
                    float a0 = expf(aux1[n >> 7]);
                    float a1 = expf(aux1[(n + 1) >> 7]);
                    float s0 = x0 + aux2[n], s1 = x1 + aux2[n + 1];
                    s0 = (s0 > 20.0f) ? s0 : log1pf(expf(s0));
                    s1 = (s1 > 20.0f) ? s1 : log1pf(expf(s1));
                    x0 = expf(-a0 * s0); x1 = expf(-a1 * s1);
                } else if (ACT == 3) {
                    x0 = 1.0f / (1.0f + expf(-(x0 + aux1[n])));
                    x1 = 1.0f / (1.0f + expf(-(x1 + aux1[n + 1])));
                }
                float2 o2; o2.x = x0; o2.y = x1;
                *(float2*)(crow + ni * 8 + qcol) = o2;
            }
        }
    }
}

// --------------------------- beta = sigmoid(h @ b_w^T) ---------------------
__global__ __launch_bounds__(512) void beta_kernel(
    const float* __restrict__ H, const float* __restrict__ BW)
{
    float* BETA = scratch_resolve(ID_BETA);
    const int m = blockIdx.x;
    const int w = threadIdx.x >> 5, lane = threadIdx.x & 31;
    const float4* hr = (const float4*)(H + (size_t)m * HIDc);
    const float4* br = (const float4*)(BW + (size_t)w * HIDc);
    float s = 0.f;
#pragma unroll 4
    for (int i = lane; i < HIDc / 4; i += 32) {
        float4 a = hr[i], b = br[i];
        s += a.x * b.x + a.y * b.y + a.z * b.z + a.w * b.w;
    }
#pragma unroll
    for (int off = 16; off > 0; off >>= 1)
        s += __shfl_xor_sync(0xffffffffu, s, off);
    if (lane == 0) BETA[(size_t)m * Hc + w] = 1.0f / (1.0f + expf(-s));
}

// --------------------------- per-head L2 norm (in place) -------------------
__global__ __launch_bounds__(128) void l2norm_kernel(int Xid, float scale)
{
    float* X = scratch_resolve(Xid);
    const int h = blockIdx.x, m = blockIdx.y;
    const int v = threadIdx.x;
    const size_t off = (size_t)m * HIDc + (size_t)h * DKc + v;
    float x = X[off];
    float s = x * x;
#pragma unroll
    for (int o = 16; o > 0; o >>= 1) s += __shfl_xor_sync(0xffffffffu, s, o);
    __shared__ float red[4];
    if ((v & 31) == 0) red[v >> 5] = s;
    __syncthreads();
    float tot = red[0] + red[1] + red[2] + red[3];
    X[off] = x * rsqrtf(tot + 1e-6f) * scale;
}

// ---------- gated RMS norm: og = rms(o)*w*sigf, emitted as fp16 hi/lo ------
__global__ __launch_bounds__(128) void gate_kernel(const float* __restrict__ NW)
{
    const float* O    = scratch_resolve(ID_O);
    const float* SIGF = scratch_resolve(ID_SIGF);
    const int h = blockIdx.x, m = blockIdx.y;
    const int v = threadIdx.x;
    const size_t off = (size_t)m * HIDc + (size_t)h * DVc + v;
    float x = O[off];
    float s = x * x;
#pragma unroll
    for (int o = 16; o > 0; o >>= 1) s += __shfl_xor_sync(0xffffffffu, s, o);
    __shared__ float red[4];
    if ((v & 31) == 0) red[v >> 5] = s;
    __syncthreads();
    float tot = red[0] + red[1] + red[2] + red[3];
    float r = rsqrtf(tot * (1.0f / DVc) + 1e-5f);
    float y = x * r * NW[v] * SIGF[off];
    __half hi = __float2half_rn(y);
    __half lo = __float2half_rn(y - __half2float(hi));
    g_hfpool[OFF_OG_HI + off] = hi;
    g_hfpool[OFF_OG_LO + off] = lo;
}

// ------------------------------ recurrent scan -----------------------------
// grid (2, H, B); 128 threads. CTA owns 64 v-columns; thread pair (shfl xor 1)
// splits the 128-k dim. State kept as 32 f32x2 pairs per thread.
// kv/o accumulation split over 4 accumulators (depth-8 chains instead of 32).
__global__ __launch_bounds__(128) void scan_kernel(
    const float* __restrict__ S0,
    float* __restrict__ Sout, int writeS)
{
    const float* Q    = scratch_resolve(ID_Q);
    const float* K    = scratch_resolve(ID_K);
    const float* V    = scratch_resolve(ID_V);
    const float* EG   = scratch_resolve(ID_EG);
    const float* BETA = scratch_resolve(ID_BETA);
    float*       O    = scratch_resolve(ID_O);

    const int vh = blockIdx.x, h = blockIdx.y, b = blockIdx.z;
    const int tid = threadIdx.x;
    const int vloc = tid >> 1, khalf = tid & 1;
    const int v = vh * 64 + vloc;
    const int ks = khalf * 64;

    __shared__ float sbuf[3][4][128];   // [stage][k,q,v,eg][128]
    __shared__ float sbeta[3];

    const size_t rowbase = (size_t)b * Tc * HIDc + (size_t)h * DKc;

    ull S[32];
    {
        const float* s0p = S0 + (((size_t)(b * Hc + h) * DKc + ks) * DVc + v);
#pragma unroll
        for (int j2 = 0; j2 < 32; j2++)
            S[j2] = f2pack(s0p[(size_t)(2 * j2) * DVc], s0p[(size_t)(2 * j2 + 1) * DVc]);
    }

    const int grp = tid >> 5, lane = tid & 31;
    const float* srcs[4] = {K, Q, V, EG};

#pragma unroll
    for (int t = 0; t < 2; t++) {
        size_t off = rowbase + (size_t)t * HIDc;
        cp16(&sbuf[t][grp][lane * 4], srcs[grp] + off + lane * 4);
        if (tid == 0) cp4(&sbeta[t], BETA + ((size_t)(b * Tc + t)) * Hc + h);
        cp_commit();
    }

    for (int t = 0; t < Tc; t++) {
        const int nt = t + 2;
        if (nt < Tc) {
            const int st = nt % 3;
            size_t off = rowbase + (size_t)nt * HIDc;
            cp16(&sbuf[st][grp][lane * 4], srcs[grp] + off + lane * 4);
            if (tid == 0) cp4(&sbeta[st], BETA + ((size_t)(b * Tc + nt)) * Hc + h);
        }
        cp_commit();
        cp_wait2();
        __syncthreads();

        const int cb = t % 3;
        const float beta = sbeta[cb];
        const float vv = sbuf[cb][2][v];

        ull k2[32];
        ull kva = 0ull, kvb = 0ull, kvc = 0ull, kvd = 0ull;
#pragma unroll
        for (int j2 = 0; j2 < 32; j2 += 4) {
            k2[j2]     = *(const ull*)&sbuf[cb][0][ks + 2 * j2];
            k2[j2 + 1] = *(const ull*)&sbuf[cb][0][ks + 2 * j2 + 2];
            k2[j2 + 2] = *(const ull*)&sbuf[cb][0][ks + 2 * j2 + 4];
            k2[j2 + 3] = *(const ull*)&sbuf[cb][0][ks + 2 * j2 + 6];
            ull e0 = *(const ull*)&sbuf[cb][3][ks + 2 * j2];
            ull e1 = *(const ull*)&sbuf[cb][3][ks + 2 * j2 + 2];
            ull e2 = *(const ull*)&sbuf[cb][3][ks + 2 * j2 + 4];
            ull e3 = *(const ull*)&sbuf[cb][3][ks + 2 * j2 + 6];
            S[j2]     = fmul2(S[j2],     e0);
            S[j2 + 1] = fmul2(S[j2 + 1], e1);
            S[j2 + 2] = fmul2(S[j2 + 2], e2);
            S[j2 + 3] = fmul2(S[j2 + 3], e3);
            kva = ffma2(k2[j2],     S[j2],     kva);
            kvb = ffma2(k2[j2 + 1], S[j2 + 1], kvb);
            kvc = ffma2(k2[j2 + 2], S[j2 + 2], kvc);
            kvd = ffma2(k2[j2 + 3], S[j2 + 3], kvd);
        }
        ull kv2 = fadd2(fadd2(kva, kvb), fadd2(kvc, kvd));
        float2 kvp = f2unpack(kv2);
        float kv = kvp.x + kvp.y;
        kv += __shfl_xor_sync(0xffffffffu, kv, 1);

        const float delta = (vv - kv) * beta;
        const ull d2 = f2pack(delta, delta);

        ull oa = 0ull, ob = 0ull, oc = 0ull, od = 0ull;
#pragma unroll
        for (int j2 = 0; j2 < 32; j2 += 4) {
            S[j2]     = ffma2(k2[j2],     d2, S[j2]);
            S[j2 + 1] = ffma2(k2[j2 + 1], d2, S[j2 + 1]);
            S[j2 + 2] = ffma2(k2[j2 + 2], d2, S[j2 + 2]);
            S[j2 + 3] = ffma2(k2[j2 + 3], d2, S[j2 + 3]);
            ull q0 = *(const ull*)&sbuf[cb][1][ks + 2 * j2];
            ull q1 = *(const ull*)&sbuf[cb][1][ks + 2 * j2 + 2];
            ull q2 = *(const ull*)&sbuf[cb][1][ks + 2 * j2 + 4];
            ull q3 = *(const ull*)&sbuf[cb][1][ks + 2 * j2 + 6];
            oa = ffma2(q0, S[j2],     oa);
            ob = ffma2(q1, S[j2 + 1], ob);
            oc = ffma2(q2, S[j2 + 2], oc);
            od = ffma2(q3, S[j2 + 3], od);
        }
        ull o2 = fadd2(fadd2(oa, ob), fadd2(oc, od));
        float2 op = f2unpack(o2);
        float o = op.x + op.y;
        o += __shfl_xor_sync(0xffffffffu, o, 1);
        if (khalf == 0)
            O[rowbase + (size_t)t * HIDc + v] = o;
        __syncthreads();
    }

    if (writeS) {
        float* sp = Sout + (((size_t)(b * Hc + h) * DKc + ks) * DVc + v);
#pragma unroll
        for (int j2 = 0; j2 < 32; j2++) {
            float2 c = f2unpack(S[j2]);
            sp[(size_t)(2 * j2) * DVc]     = c.x;
            sp[(size_t)(2 * j2 + 1) * DVc] = c.y;
        }
    }
}

// ------------------------------ host launcher ------------------------------
extern "C" void kernel_launch(void* const* d_in, const int* in_sizes, int n_in,
                              void* d_out, int out_size)
{
    const float* h      = (const float*)d_in[0];
    const float* S0     = (const float*)d_in[1];
    const float* q_w    = (const float*)d_in[2];
    const float* k_w    = (const float*)d_in[3];
    const float* v_w    = (const float*)d_in[4];
    const float* f_w0   = (const float*)d_in[5];
    const float* f_w1   = (const float*)d_in[6];
    const float* b_w    = (const float*)d_in[7];
    const float* A_log  = (const float*)d_in[8];
    const float* dt_b   = (const float*)d_in[9];
    const float* g_w0   = (const float*)d_in[10];
    const float* g_w1   = (const float*)d_in[11];
    const float* g_b1   = (const float*)d_in[12];
    const float* o_nw   = (const float*)d_in[13];
    const float* o_w    = (const float*)d_in[14];
    float* out = (float*)d_out;

    cudaFuncSetAttribute(mma_gemm<0>, cudaFuncAttributeMaxDynamicSharedMemorySize, GSMEM);
    cudaFuncSetAttribute(mma_gemm<1>, cudaFuncAttributeMaxDynamicSharedMemorySize, GSMEM);
    cudaFuncSetAttribute(mma_gemm<2>, cudaFuncAttributeMaxDynamicSharedMemorySize, GSMEM);
    cudaFuncSetAttribute(mma_gemm<3>, cudaFuncAttributeMaxDynamicSharedMemorySize, GSMEM);

    const dim3 g_big(HIDc / 128, Mc / 128);   // (16, 64)
    const dim3 g_n128(1, Mc / 128);           // (1, 64)

    // ---- split inputs into fp16 hi/lo ----
    split_kernel<<<(Mc * HIDc) / 1024, 256>>>(h,    -1, OFF_HB_HI,  OFF_HB_LO);
    split_kernel<<<(HIDc * HIDc) / 1024, 256>>>(q_w, -1, OFF_WQ_HI,  OFF_WQ_LO);
    split_kernel<<<(HIDc * HIDc) / 1024, 256>>>(k_w, -1, OFF_WK_HI,  OFF_WK_LO);
    split_kernel<<<(HIDc * HIDc) / 1024, 256>>>(v_w, -1, OFF_WV_HI,  OFF_WV_LO);
    split_kernel<<<(HIDc * HIDc) / 1024, 256>>>(o_w, -1, OFF_WO_HI,  OFF_WO_LO);
    split_kernel<<<(128 * HIDc) / 1024, 256>>>(f_w0, -1, OFF_FW0_HI, OFF_FW0_LO);
    split_kernel<<<(128 * HIDc) / 1024, 256>>>(g_w0, -1, OFF_GW0_HI, OFF_GW0_LO);
    split_kernel<<<(HIDc * 128) / 1024, 256>>>(f_w1, -1, OFF_FW1_HI, OFF_FW1_LO);
    split_kernel<<<(HIDc * 128) / 1024, 256>>>(g_w1, -1, OFF_GW1_HI, OFF_GW1_LO);

    // ---- projections (silu fused) ----
    mma_gemm<1><<<g_big, 256, GSMEM>>>(OFF_HB_HI, OFF_HB_LO, OFF_WQ_HI,
                                       nullptr, ID_Q, HIDc, HIDc, nullptr, nullptr);
    mma_gemm<1><<<g_big, 256, GSMEM>>>(OFF_HB_HI, OFF_HB_LO, OFF_WK_HI,
                                       nullptr, ID_K, HIDc, HIDc, nullptr, nullptr);
    mma_gemm<1><<<g_big, 256, GSMEM>>>(OFF_HB_HI, OFF_HB_LO, OFF_WV_HI,
                                       nullptr, ID_V, HIDc, HIDc, nullptr, nullptr);

    // ---- gate: eg = exp(-exp(A_log)*softplus((h@f_w0^T)@f_w1^T + dt_bias)) ----
    mma_gemm<0><<<g_n128, 256, GSMEM>>>(OFF_HB_HI, OFF_HB_LO, OFF_FW0_HI,
                                        nullptr, ID_TMP, 128, HIDc, nullptr, nullptr);
    split_kernel<<<(Mc * 128) / 1024, 256>>>(nullptr, ID_TMP, OFF_TMP_HI, OFF_TMP_LO);
    mma_gemm<2><<<g_big, 256, GSMEM>>>(OFF_TMP_HI, OFF_TMP_LO, OFF_FW1_HI,
                                       nullptr, ID_EG, HIDc, 128, A_log, dt_b);

    // ---- beta + l2 norms ----
    beta_kernel<<<Mc, 512>>>(h, b_w);
    l2norm_kernel<<<dim3(Hc, Mc), 128>>>(ID_Q, 0.08838834764831845f);
    l2norm_kernel<<<dim3(Hc, Mc), 128>>>(ID_K, 1.0f);

    // ---- output gate factor: sigf = sigmoid((h@g_w0^T)@g_w1^T + g_b1) ----
    mma_gemm<0><<<g_n128, 256, GSMEM>>>(OFF_HB_HI, OFF_HB_LO, OFF_GW0_HI,
                                        nullptr, ID_TMP, 128, HIDc, nullptr, nullptr);
    split_kernel<<<(Mc * 128) / 1024, 256>>>(nullptr, ID_TMP, OFF_TMP_HI, OFF_TMP_LO);
    mma_gemm<3><<<g_big, 256, GSMEM>>>(OFF_TMP_HI, OFF_TMP_LO, OFF_GW1_HI,
                                       nullptr, ID_SIGF, HIDc, 128, g_b1, nullptr);

    // ---- recurrent scan ----
    const size_t out_elems = (size_t)Mc * HIDc;                 // 16,777,216
    const size_t s_elems   = (size_t)Bc * Hc * DKc * DVc;       //  1,048,576
    const int writeS = ((size_t)out_size >= out_elems + s_elems) ? 1 : 0;
    scan_kernel<<<dim3(2, Hc, Bc), 128>>>(S0, out + out_elems, writeS);

    // ---- gated rms norm (emits fp16 hi/lo) + final projection ----
    gate_kernel<<<dim3(Hc, Mc), 128>>>(o_nw);
    mma_gemm<0><<<g_big, 256, GSMEM>>>(OFF_OG_HI, OFF_OG_LO, OFF_WO_HI,
                                       out, -1, HIDc, HIDc, nullptr, nullptr);
}

// round 11
// speedup vs baseline: 1.2686x; 1.0166x over previous
#include <cuda_runtime.h>
#include <cuda_fp16.h>
#include <cuda_bf16.h>
#include <cstdint>

// ---------------------------------------------------------------------------
// KimiDeltaAttention — mma.sync fp16 GEMMs (A hi/lo split, W fp16; 2 MMAs per
// product, fp32 accum) + fp32 scan (256-thread, 4-way k-split).
// B=4, T=2048, HID=2048, H=16, DK=DV=128
// compute_103 PTX only (no 'a' features): tensor path = mma.sync m16n8k16 f16.
// ---------------------------------------------------------------------------

#define Bc 4
#define Tc 2048
#define HIDc 2048
#define Hc 16
#define DKc 128
#define DVc 128
#define Mc (Bc * Tc)            // 8192 rows

typedef unsigned long long ull;
typedef unsigned int u32;

// ------------------------- fp32 scratch (device globals) -------------------
__device__ float g_q   [(size_t)Mc * HIDc];
__device__ float g_k   [(size_t)Mc * HIDc];
__device__ float g_v   [(size_t)Mc * HIDc];
__device__ float g_eg  [(size_t)Mc * HIDc];   // exp(gate)
__device__ float g_sigf[(size_t)Mc * HIDc];   // sigmoid(factor)
__device__ float g_o   [(size_t)Mc * HIDc];
__device__ float g_tmp [(size_t)Mc * 128];    // low-rank intermediate
__device__ float g_beta[(size_t)Mc * Hc];

#define ID_Q    0
#define ID_K    1
#define ID_V    2
#define ID_EG   3
#define ID_SIGF 4
#define ID_O    5
#define ID_TMP  6
#define ID_BETA 7

__device__ __forceinline__ float* scratch_resolve(int id) {
    switch (id) {
        case ID_Q:    return g_q;
        case ID_K:    return g_k;
        case ID_V:    return g_v;
        case ID_EG:   return g_eg;
        case ID_SIGF: return g_sigf;
        case ID_O:    return g_o;
        case ID_TMP:  return g_tmp;
        default:      return g_beta;
    }
}

// ------------------------- fp16 split pool ---------------------------------
constexpr size_t OFF_HB_HI  = 0;
constexpr size_t OFF_HB_LO  = OFF_HB_HI  + (size_t)Mc * HIDc;
constexpr size_t OFF_WQ_HI  = OFF_HB_LO  + (size_t)Mc * HIDc;
constexpr size_t OFF_WQ_LO  = OFF_WQ_HI  + (size_t)HIDc * HIDc;
constexpr size_t OFF_WK_HI  = OFF_WQ_LO  + (size_t)HIDc * HIDc;
constexpr size_t OFF_WK_LO  = OFF_WK_HI  + (size_t)HIDc * HIDc;
constexpr size_t OFF_WV_HI  = OFF_WK_LO  + (size_t)HIDc * HIDc;
constexpr size_t OFF_WV_LO  = OFF_WV_HI  + (size_t)HIDc * HIDc;
constexpr size_t OFF_WO_HI  = OFF_WV_LO  + (size_t)HIDc * HIDc;
constexpr size_t OFF_WO_LO  = OFF_WO_HI  + (size_t)HIDc * HIDc;
constexpr size_t OFF_FW0_HI = OFF_WO_LO  + (size_t)HIDc * HIDc;
constexpr size_t OFF_FW0_LO = OFF_FW0_HI + (size_t)128 * HIDc;
constexpr size_t OFF_GW0_HI = OFF_FW0_LO + (size_t)128 * HIDc;
constexpr size_t OFF_GW0_LO = OFF_GW0_HI + (size_t)128 * HIDc;
constexpr size_t OFF_FW1_HI = OFF_GW0_LO + (size_t)128 * HIDc;
constexpr size_t OFF_FW1_LO = OFF_FW1_HI + (size_t)HIDc * 128;
constexpr size_t OFF_GW1_HI = OFF_FW1_LO + (size_t)HIDc * 128;
constexpr size_t OFF_GW1_LO = OFF_GW1_HI + (size_t)HIDc * 128;
constexpr size_t OFF_TMP_HI = OFF_GW1_LO + (size_t)HIDc * 128;
constexpr size_t OFF_TMP_LO = OFF_TMP_HI + (size_t)Mc * 128;
constexpr size_t OFF_OG_HI  = OFF_TMP_LO + (size_t)Mc * 128;
constexpr size_t OFF_OG_LO  = OFF_OG_HI  + (size_t)Mc * HIDc;
constexpr size_t HF_TOTAL   = OFF_OG_LO  + (size_t)Mc * HIDc;

__device__ __half g_hfpool[HF_TOTAL];

// ------------------------------ f32x2 helpers ------------------------------
__device__ __forceinline__ ull f2pack(float a, float b) {
    ull r; asm("mov.b64 %0, {%1, %2};" : "=l"(r) : "f"(a), "f"(b)); return r;
}
__device__ __forceinline__ float2 f2unpack(ull x) {
    float2 r; asm("mov.b64 {%0, %1}, %2;" : "=f"(r.x), "=f"(r.y) : "l"(x)); return r;
}
__device__ __forceinline__ ull ffma2(ull a, ull b, ull c) {
    ull d; asm("fma.rn.f32x2 %0, %1, %2, %3;" : "=l"(d) : "l"(a), "l"(b), "l"(c)); return d;
}
__device__ __forceinline__ ull fmul2(ull a, ull b) {
    ull d; asm("mul.rn.f32x2 %0, %1, %2;" : "=l"(d) : "l"(a), "l"(b)); return d;
}
__device__ __forceinline__ ull fadd2(ull a, ull b) {
    ull d; asm("add.rn.f32x2 %0, %1, %2;" : "=l"(d) : "l"(a), "l"(b)); return d;
}

// ------------------------------ async copy ---------------------------------
__device__ __forceinline__ void cp16(void* s, const void* g) {
    u32 sa = (u32)__cvta_generic_to_shared(s);
    asm volatile("cp.async.ca.shared.global [%0], [%1], 16;" :: "r"(sa), "l"(g));
}
__device__ __forceinline__ void cp16u(u32 s, const void* g) {
    asm volatile("cp.async.cg.shared.global [%0], [%1], 16;" :: "r"(s), "l"(g));
}
__device__ __forceinline__ void cp4(void* s, const void* g) {
    u32 sa = (u32)__cvta_generic_to_shared(s);
    asm volatile("cp.async.ca.shared.global [%0], [%1], 4;" :: "r"(sa), "l"(g));
}
__device__ __forceinline__ void cp_commit() { asm volatile("cp.async.commit_group;"); }

__device__ __forceinline__ u32 smem_u32(const void* p) {
    return (u32)__cvta_generic_to_shared(p);
}

// ------------------------------ mma helpers --------------------------------
__device__ __forceinline__ void mma16816(float* c, const u32* a, const u32* b) {
    asm volatile(
        "mma.sync.aligned.m16n8k16.row.col.f32.f16.f16.f32 "
        "{%0,%1,%2,%3}, {%4,%5,%6,%7}, {%8,%9}, {%0,%1,%2,%3};"
        : "+f"(c[0]), "+f"(c[1]), "+f"(c[2]), "+f"(c[3])
        : "r"(a[0]), "r"(a[1]), "r"(a[2]), "r"(a[3]), "r"(b[0]), "r"(b[1]));
}
__device__ __forceinline__ void ldsm4(u32* r, u32 addr) {
    asm volatile("ldmatrix.sync.aligned.m8n8.x4.shared.b16 {%0,%1,%2,%3}, [%4];"
        : "=r"(r[0]), "=r"(r[1]), "=r"(r[2]), "=r"(r[3]) : "r"(addr));
}

// ------------------------------ split kernel -------------------------------
// x -> hi = fp16(x), lo = fp16(x - hi). 4 elems/thread, vectorized.
__global__ __launch_bounds__(256) void split_kernel(
    const float* __restrict__ ext, int srcId, size_t off_hi, size_t off_lo)
{
    const float* src = (srcId >= 0) ? scratch_resolve(srcId) : ext;
    size_t i = ((size_t)blockIdx.x * 256 + threadIdx.x) * 4;
    float4 x = *(const float4*)(src + i);
    __half h0 = __float2half_rn(x.x), h1 = __float2half_rn(x.y);
    __half h2 = __float2half_rn(x.z), h3 = __float2half_rn(x.w);
    __half l0 = __float2half_rn(x.x - __half2float(h0));
    __half l1 = __float2half_rn(x.y - __half2float(h1));
    __half l2 = __float2half_rn(x.z - __half2float(h2));
    __half l3 = __float2half_rn(x.w - __half2float(h3));
    uint2 ph, pl;
    ph.x = (u32)__half_as_ushort(h0) | ((u32)__half_as_ushort(h1) << 16);
    ph.y = (u32)__half_as_ushort(h2) | ((u32)__half_as_ushort(h3) << 16);
    pl.x = (u32)__half_as_ushort(l0) | ((u32)__half_as_ushort(l1) << 16);
    pl.y = (u32)__half_as_ushort(l2) | ((u32)__half_as_ushort(l3) << 16);
    *(uint2*)(g_hfpool + off_hi + i) = ph;
    *(uint2*)(g_hfpool + off_lo + i) = pl;
}

// ------------------------- mma.sync fp16 GEMM ------------------------------
// C[M,N] = act( A[M,K] @ W[N,K]^T ), A split hi/lo (error-free), W fp16-hi:
//   D += Ahi*Whi + Alo*Whi   (fp32 accumulators; rel err ~3.5e-4 end to end)
// CTA tile 128x128, 256 thr (8 warps, 2x4; warp tile 64x32), BK=32, 2-stage
// cp.async pipeline, XOR-swizzled smem, ldmatrix fragment loads.
// ACT: 0 none | 1 silu | 2 kda-gate->exp | 3 sigmoid(x+aux1[n])
constexpr int BKg         = 32;
constexpr int TILE_BYTES  = 128 * BKg * 2;     // 8 KB
constexpr int STAGE_BYTES = 3 * TILE_BYTES;    // 24 KB (Ahi, Alo, Whi)
constexpr int GSMEM       = 2 * STAGE_BYTES;   // 48 KB

template <int ACT>
__global__ __launch_bounds__(256) void mma_gemm(
    size_t a_hi, size_t a_lo, size_t w_hi,
    float* __restrict__ Cext, int Cid, int Ntot, int Ktot,
    const float* __restrict__ aux1, const float* __restrict__ aux2)
{
    extern __shared__ char dsm[];
    const u32 sb = smem_u32(dsm);
    const int tid = threadIdx.x, lane = tid & 31, wid = tid >> 5;
    const int warp_m = wid & 1, warp_n = wid >> 1;    // 2 x 4 warp grid
    const int bm = blockIdx.y, bn = blockIdx.x;

    const __half* srcs[3] = {
        g_hfpool + a_hi + (size_t)bm * 128 * Ktot,
        g_hfpool + a_lo + (size_t)bm * 128 * Ktot,
        g_hfpool + w_hi + (size_t)bn * 128 * Ktot };

    float acc[4][4][4];
#pragma unroll
    for (int i = 0; i < 4; i++)
#pragma unroll
        for (int j = 0; j < 4; j++)
#pragma unroll
            for (int e = 0; e < 4; e++) acc[i][j][e] = 0.f;

    const int NC = Ktot / BKg;
    const int jq = lane >> 3, rq = lane & 7;
    const int jlow = jq & 1, jhi = jq >> 1;

    // --- stage loader: 3 tiles x 128 rows x 4 x 16B groups, swizzled
    auto load_stage = [&](int stage, int c) {
        u32 base = sb + (u32)stage * STAGE_BYTES;
#pragma unroll
        for (int t = 0; t < 3; t++) {
            const __half* src = srcs[t] + (size_t)c * BKg;
            u32 tb = base + (u32)t * TILE_BYTES;
#pragma unroll
            for (int i = 0; i < 2; i++) {
                int idx = tid + i * 256;                 // 0..511
                u32 row = (u32)(idx >> 2), g = (u32)(idx & 3);
                u32 so = tb + row * 64u + ((g ^ (row & 3u)) * 16u);
                cp16u(so, (const char*)(src + (size_t)row * Ktot) + g * 16);
            }
        }
    };

    load_stage(0, 0); cp_commit();

    for (int c = 0; c < NC; c++) {
        if (c + 1 < NC) {
            load_stage((c + 1) & 1, c + 1); cp_commit();
            asm volatile("cp.async.wait_group 1;" ::: "memory");
        } else {
            asm volatile("cp.async.wait_group 0;" ::: "memory");
        }
        __syncthreads();

        const u32 base = sb + (u32)(c & 1) * STAGE_BYTES;
        const u32 ah = base, al = base + TILE_BYTES;
        const u32 wh = base + 2 * TILE_BYTES;

#pragma unroll
        for (int ks = 0; ks < 2; ks++) {
            const u32 g = (u32)(ks * 2 + jhi);
            u32 a_hi_f[4][4], a_lo_f[4][4];
#pragma unroll
            for (int mi = 0; mi < 4; mi++) {
                u32 row = (u32)(warp_m * 64 + mi * 16 + jlow * 8 + rq);
                u32 off = row * 64u + ((g ^ (row & 3u)) * 16u);
                ldsm4(a_hi_f[mi], ah + off);
                ldsm4(a_lo_f[mi], al + off);
            }
            u32 b_hi_f[4][2];
#pragma unroll
            for (int pi = 0; pi < 2; pi++) {
                u32 row = (u32)(warp_n * 32 + pi * 16 + jlow * 8 + rq);
                u32 off = row * 64u + ((g ^ (row & 3u)) * 16u);
                u32 t0[4];
                ldsm4(t0, wh + off);
                b_hi_f[2*pi][0] = t0[0]; b_hi_f[2*pi][1] = t0[2];
                b_hi_f[2*pi+1][0] = t0[1]; b_hi_f[2*pi+1][1] = t0[3];
            }
#pragma unroll
            for (int mi = 0; mi < 4; mi++)
#pragma unroll
                for (int ni = 0; ni < 4; ni++) {
                    mma16816(acc[mi][ni], a_hi_f[mi], b_hi_f[ni]);
                    mma16816(acc[mi][ni], a_lo_f[mi], b_hi_f[ni]);
                }
        }
        __syncthreads();
    }

    // epilogue
    float* C = (Cid >= 0) ? scratch_resolve(Cid) : Cext;
    const int qrow = lane >> 2, qcol = (lane & 3) * 2;
    const int n_warp0 = bn * 128 + warp_n * 32;
#pragma unroll
    for (int mi = 0; mi < 4; mi++) {
#pragma unroll
        for (int half = 0; half < 2; half++) {
            const int m = bm * 128 + warp_m * 64 + mi * 16 + half * 8 + qrow;
            float* crow = C + (size_t)m * Ntot + n_warp0;
#pragma unroll
            for (int ni = 0; ni < 4; ni++) {
                float x0 = acc[mi][ni][half * 2];
                float x1 = acc[mi][ni][half * 2 + 1];
                const int n = n_warp0 + ni * 8 + qcol;
                if (ACT == 1) {
                    x0 = x0 / (1.0f + expf(-x0));
                    x1 = x1 / (1.0f + expf(-x1));
                } else if (ACT == 2) {
                    float a0 = expf(aux1[n >> 7]);
                    float a1 = expf(aux1[(n + 1) >> 7]);
                    float s0 = x0 + aux2[n], s1 = x1 + aux2[n + 1];
                    s0 = (s0 > 20.0f) ? s0 : log1pf(expf(s0));
                    s1 = (s1 > 20.0f) ? s1 : log1pf(expf(s1));
                    x0 = expf(-a0 * s0); x1 = expf(-a1 * s1);
                } else if (ACT == 3) {
                    x0 = 1.0f / (1.0f + expf(-(x0 + aux1[n])));
                    x1 = 1.0f / (1.0f + expf(-(x1 + aux1[n + 1])));
                }
                float2 o2; o2.x = x0; o2.y = x1;
                *(float2*)(crow + ni * 8 + qcol) = o2;
            }
        }
    }
}

// --------------------------- beta = sigmoid(h @ b_w^T) ---------------------
__global__ __launch_bounds__(512) void beta_kernel(
    const float* __restrict__ H, const float* __restrict__ BW)
{
    float* BETA = scratch_resolve(ID_BETA);
    const int m = blockIdx.x;
    const int w = threadIdx.x >> 5, lane = threadIdx.x & 31;
    const float4* hr = (const float4*)(H + (size_t)m * HIDc);
    const float4* br = (const float4*)(BW + (size_t)w * HIDc);
    float s = 0.f;
#pragma unroll 4
    for (int i = lane; i < HIDc / 4; i += 32) {
        float4 a = hr[i], b = br[i];
        s += a.x * b.x + a.y * b.y + a.z * b.z + a.w * b.w;
    }
#pragma unroll
    for (int off = 16; off > 0; off >>= 1)
        s += __shfl_xor_sync(0xffffffffu, s, off);
    if (lane == 0) BETA[(size_t)m * Hc + w] = 1.0f / (1.0f + expf(-s));
}

// --------------------------- per-head L2 norm (in place) -------------------
__global__ __launch_bounds__(128) void l2norm_kernel(int Xid, float scale)
{
    float* X = scratch_resolve(Xid);
    const int h = blockIdx.x, m = blockIdx.y;
    const int v = threadIdx.x;
    const size_t off = (size_t)m * HIDc + (size_t)h * DKc + v;
    float x = X[off];
    float s = x * x;
#pragma unroll
    for (int o = 16; o > 0; o >>= 1) s += __shfl_xor_sync(0xffffffffu, s, o);
    __shared__ float red[4];
    if ((v & 31) == 0) red[v >> 5] = s;
    __syncthreads();
    float tot = red[0] + red[1] + red[2] + red[3];
    X[off] = x * rsqrtf(tot + 1e-6f) * scale;
}

// ---------- gated RMS norm: og = rms(o)*w*sigf, emitted as fp16 hi/lo ------
__global__ __launch_bounds__(128) void gate_kernel(const float* __restrict__ NW)
{
    const float* O    = scratch_resolve(ID_O);
    const float* SIGF = scratch_resolve(ID_SIGF);
    const int h = blockIdx.x, m = blockIdx.y;
    const int v = threadIdx.x;
    const size_t off = (size_t)m * HIDc + (size_t)h * DVc + v;
    float x = O[off];
    float s = x * x;
#pragma unroll
    for (int o = 16; o > 0; o >>= 1) s += __shfl_xor_sync(0xffffffffu, s, o);
    __shared__ float red[4];
    if ((v & 31) == 0) red[v >> 5] = s;
    __syncthreads();
    float tot = red[0] + red[1] + red[2] + red[3];
    float r = rsqrtf(tot * (1.0f / DVc) + 1e-5f);
    float y = x * r * NW[v] * SIGF[off];
    __half hi = __float2half_rn(y);
    __half lo = __float2half_rn(y - __half2float(hi));
    g_hfpool[OFF_OG_HI + off] = hi;
    g_hfpool[OFF_OG_LO + off] = lo;
}

// ------------------------------ recurrent scan -----------------------------
// grid (2, H, B); 256 threads. CTA owns 64 v-cols; 4 threads split the 128-k
// dim (kq = tid&3, 32 k each, 16 state pairs/thread). 4 smem stages, prefetch
// distance 2 -> single barrier per step. Rows skewed +4 floats per 32-block
// so the 4 k-quarters hit distinct banks.
#define SROW 144
#define SKW(i) ((i) + ((((u32)(i)) >> 5) << 2))

__global__ __launch_bounds__(256) void scan_kernel(
    const float* __restrict__ S0,
    float* __restrict__ Sout, int writeS)
{
    const float* Q    = scratch_resolve(ID_Q);
    const float* K    = scratch_resolve(ID_K);
    const float* V    = scratch_resolve(ID_V);
    const float* EG   = scratch_resolve(ID_EG);
    const float* BETA = scratch_resolve(ID_BETA);
    float*       O    = scratch_resolve(ID_O);

    const int vh = blockIdx.x, h = blockIdx.y, b = blockIdx.z;
    const int tid = threadIdx.x;
    const int vloc = tid >> 2, kq = tid & 3;
    const int v = vh * 64 + vloc;
    const int ks = kq * 32;

    __shared__ float sbuf[4][4][SROW];   // [stage][k,q,v,eg][128 skewed]
    __shared__ float sbeta[4];

    const size_t rowbase = (size_t)b * Tc * HIDc + (size_t)h * DKc;

    // state S[k in ks..ks+31][v], 16 f32x2 pairs
    ull S[16];
    {
        const float* s0p = S0 + (((size_t)(b * Hc + h) * DKc + ks) * DVc + v);
#pragma unroll
        for (int j2 = 0; j2 < 16; j2++)
            S[j2] = f2pack(s0p[(size_t)(2 * j2) * DVc], s0p[(size_t)(2 * j2 + 1) * DVc]);
    }

    const int grp = tid >> 6, idx = tid & 63;
    const float* srcs[4] = {K, Q, V, EG};

    // prologue: prefetch t=0,1
#pragma unroll
    for (int t = 0; t < 2; t++) {
        if (idx < 32)
            cp16(&sbuf[t][grp][idx * 4 + ((idx >> 3) << 2)],
                 srcs[grp] + rowbase + (size_t)t * HIDc + idx * 4);
        if (tid == 0) cp4(&sbeta[t], BETA + ((size_t)(b * Tc + t)) * Hc + h);
        cp_commit();
    }

    for (int t = 0; t < Tc; t++) {
        if (t + 2 < Tc) {
            const int st = (t + 2) & 3;
            if (idx < 32)
                cp16(&sbuf[st][grp][idx * 4 + ((idx >> 3) << 2)],
                     srcs[grp] + rowbase + (size_t)(t + 2) * HIDc + idx * 4);
            if (tid == 0) cp4(&sbeta[st], BETA + ((size_t)(b * Tc + t + 2)) * Hc + h);
            cp_commit();
            asm volatile("cp.async.wait_group 2;" ::: "memory");
        } else {
            asm volatile("cp.async.wait_group 0;" ::: "memory");
        }
        __syncthreads();

        const int cb = t & 3;
        const float beta = sbeta[cb];
        const float vv = sbuf[cb][2][SKW(v)];
        const int kb = ks + kq * 4;        // skewed base for this k-quarter

        ull k2[16];
        ull kva = 0ull, kvb = 0ull;
#pragma unroll
        for (int j2 = 0; j2 < 16; j2 += 2) {
            k2[j2]     = *(const ull*)&sbuf[cb][0][kb + 2 * j2];
            k2[j2 + 1] = *(const ull*)&sbuf[cb][0][kb + 2 * j2 + 2];
            ull e0 = *(const ull*)&sbuf[cb][3][kb + 2 * j2];
            ull e1 = *(const ull*)&sbuf[cb][3][kb + 2 * j2 + 2];
            S[j2]     = fmul2(S[j2],     e0);
            S[j2 + 1] = fmul2(S[j2 + 1], e1);
            kva = ffma2(k2[j2],     S[j2],     kva);
            kvb = ffma2(k2[j2 + 1], S[j2 + 1], kvb);
        }
        ull kv2 = fadd2(kva, kvb);
        float2 kvp = f2unpack(kv2);
        float kv = kvp.x + kvp.y;
        kv += __shfl_xor_sync(0xffffffffu, kv, 1);
        kv += __shfl_xor_sync(0xffffffffu, kv, 2);

        const float delta = (vv - kv) * beta;
        const ull d2 = f2pack(delta, delta);

        ull oa = 0ull, ob = 0ull;
#pragma unroll
        for (int j2 = 0; j2 < 16; j2 += 2) {
            S[j2]     = ffma2(k2[j2],     d2, S[j2]);
            S[j2 + 1] = ffma2(k2[j2 + 1], d2, S[j2 + 1]);
            ull q0 = *(const ull*)&sbuf[cb][1][kb + 2 * j2];
            ull q1 = *(const ull*)&sbuf[cb][1][kb + 2 * j2 + 2];
            oa = ffma2(q0, S[j2],     oa);
            ob = ffma2(q1, S[j2 + 1], ob);
        }
        ull o2 = fadd2(oa, ob);
        float2 op = f2unpack(o2);
        float o = op.x + op.y;
        o += __shfl_xor_sync(0xffffffffu, o, 1);
        o += __shfl_xor_sync(0xffffffffu, o, 2);
        if (kq == 0)
            O[rowbase + (size_t)t * HIDc + v] = o;
        // no end barrier: next prefetch targets stage (t+3)&3, last read at
        // iteration t-1 and protected by that iteration's barrier.
    }

    if (writeS) {
        float* sp = Sout + (((size_t)(b * Hc + h) * DKc + ks) * DVc + v);
#pragma unroll
        for (int j2 = 0; j2 < 16; j2++) {
            float2 c = f2unpack(S[j2]);
            sp[(size_t)(2 * j2) * DVc]     = c.x;
            sp[(size_t)(2 * j2 + 1) * DVc] = c.y;
        }
    }
}

// ------------------------------ host launcher ------------------------------
extern "C" void kernel_launch(void* const* d_in, const int* in_sizes, int n_in,
                              void* d_out, int out_size)
{
    const float* h      = (const float*)d_in[0];
    const float* S0     = (const float*)d_in[1];
    const float* q_w    = (const float*)d_in[2];
    const float* k_w    = (const float*)d_in[3];
    const float* v_w    = (const float*)d_in[4];
    const float* f_w0   = (const float*)d_in[5];
    const float* f_w1   = (const float*)d_in[6];
    const float* b_w    = (const float*)d_in[7];
    const float* A_log  = (const float*)d_in[8];
    const float* dt_b   = (const float*)d_in[9];
    const float* g_w0   = (const float*)d_in[10];
    const float* g_w1   = (const float*)d_in[11];
    const float* g_b1   = (const float*)d_in[12];
    const float* o_nw   = (const float*)d_in[13];
    const float* o_w    = (const float*)d_in[14];
    float* out = (float*)d_out;

    cudaFuncSetAttribute(mma_gemm<0>, cudaFuncAttributeMaxDynamicSharedMemorySize, GSMEM);
    cudaFuncSetAttribute(mma_gemm<1>, cudaFuncAttributeMaxDynamicSharedMemorySize, GSMEM);
    cudaFuncSetAttribute(mma_gemm<2>, cudaFuncAttributeMaxDynamicSharedMemorySize, GSMEM);
    cudaFuncSetAttribute(mma_gemm<3>, cudaFuncAttributeMaxDynamicSharedMemorySize, GSMEM);

    const dim3 g_big(HIDc / 128, Mc / 128);   // (16, 64)
    const dim3 g_n128(1, Mc / 128);           // (1, 64)

    // ---- split inputs into fp16 hi/lo ----
    split_kernel<<<(Mc * HIDc) / 1024, 256>>>(h,    -1, OFF_HB_HI,  OFF_HB_LO);
    split_kernel<<<(HIDc * HIDc) / 1024, 256>>>(q_w, -1, OFF_WQ_HI,  OFF_WQ_LO);
    split_kernel<<<(HIDc * HIDc) / 1024, 256>>>(k_w, -1, OFF_WK_HI,  OFF_WK_LO);
    split_kernel<<<(HIDc * HIDc) / 1024, 256>>>(v_w, -1, OFF_WV_HI,  OFF_WV_LO);
    split_kernel<<<(HIDc * HIDc) / 1024, 256>>>(o_w, -1, OFF_WO_HI,  OFF_WO_LO);
    split_kernel<<<(128 * HIDc) / 1024, 256>>>(f_w0, -1, OFF_FW0_HI, OFF_FW0_LO);
    split_kernel<<<(128 * HIDc) / 1024, 256>>>(g_w0, -1, OFF_GW0_HI, OFF_GW0_LO);
    split_kernel<<<(HIDc * 128) / 1024, 256>>>(f_w1, -1, OFF_FW1_HI, OFF_FW1_LO);
    split_kernel<<<(HIDc * 128) / 1024, 256>>>(g_w1, -1, OFF_GW1_HI, OFF_GW1_LO);

    // ---- projections (silu fused) ----
    mma_gemm<1><<<g_big, 256, GSMEM>>>(OFF_HB_HI, OFF_HB_LO, OFF_WQ_HI,
                                       nullptr, ID_Q, HIDc, HIDc, nullptr, nullptr);
    mma_gemm<1><<<g_big, 256, GSMEM>>>(OFF_HB_HI, OFF_HB_LO, OFF_WK_HI,
                                       nullptr, ID_K, HIDc, HIDc, nullptr, nullptr);
    mma_gemm<1><<<g_big, 256, GSMEM>>>(OFF_HB_HI, OFF_HB_LO, OFF_WV_HI,
                                       nullptr, ID_V, HIDc, HIDc, nullptr, nullptr);

    // ---- gate: eg = exp(-exp(A_log)*softplus((h@f_w0^T)@f_w1^T + dt_bias)) ----
    mma_gemm<0><<<g_n128, 256, GSMEM>>>(OFF_HB_HI, OFF_HB_LO, OFF_FW0_HI,
                                        nullptr, ID_TMP, 128, HIDc, nullptr, nullptr);
    split_kernel<<<(Mc * 128) / 1024, 256>>>(nullptr, ID_TMP, OFF_TMP_HI, OFF_TMP_LO);
    mma_gemm<2><<<g_big, 256, GSMEM>>>(OFF_TMP_HI, OFF_TMP_LO, OFF_FW1_HI,
                                       nullptr, ID_EG, HIDc, 128, A_log, dt_b);

    // ---- beta + l2 norms ----
    beta_kernel<<<Mc, 512>>>(h, b_w);
    l2norm_kernel<<<dim3(Hc, Mc), 128>>>(ID_Q, 0.08838834764831845f);
    l2norm_kernel<<<dim3(Hc, Mc), 128>>>(ID_K, 1.0f);

    // ---- output gate factor: sigf = sigmoid((h@g_w0^T)@g_w1^T + g_b1) ----
    mma_gemm<0><<<g_n128, 256, GSMEM>>>(OFF_HB_HI, OFF_HB_LO, OFF_GW0_HI,
                                        nullptr, ID_TMP, 128, HIDc, nullptr, nullptr);
    split_kernel<<<(Mc * 128) / 1024, 256>>>(nullptr, ID_TMP, OFF_TMP_HI, OFF_TMP_LO);
    mma_gemm<3><<<g_big, 256, GSMEM>>>(OFF_TMP_HI, OFF_TMP_LO, OFF_GW1_HI,
                                       nullptr, ID_SIGF, HIDc, 128, g_b1, nullptr);

    // ---- recurrent scan ----
    const size_t out_elems = (size_t)Mc * HIDc;                 // 16,777,216
    const size_t s_elems   = (size_t)Bc * Hc * DKc * DVc;       //  1,048,576
    const int writeS = ((size_t)out_size >= out_elems + s_elems) ? 1 : 0;
    scan_kernel<<<dim3(2, Hc, Bc), 256>>>(S0, out + out_elems, writeS);

    // ---- gated rms norm (emits fp16 hi/lo) + final projection ----
    gate_kernel<<<dim3(Hc, Mc), 128>>>(o_nw);
    mma_gemm<0><<<g_big, 256, GSMEM>>>(OFF_OG_HI, OFF_OG_LO, OFF_WO_HI,
                                       out, -1, HIDc, HIDc, nullptr, nullptr);
}

// round 13
// speedup vs baseline: 1.3263x; 1.0455x over previous
#include <cuda_runtime.h>
#include <cuda_fp16.h>
#include <cuda_bf16.h>
#include <cstdint>

// ---------------------------------------------------------------------------
// KimiDeltaAttention — mma.sync fp16 GEMMs (A hi/lo split, W fp16; 2 MMAs per
// product, fp32 accum; 3-stage pipeline, fused l2norm epilogue) + fp32 scan.
// B=4, T=2048, HID=2048, H=16, DK=DV=128
// compute_103 PTX only (no 'a' features): tensor path = mma.sync m16n8k16 f16.
// ---------------------------------------------------------------------------

#define Bc 4
#define Tc 2048
#define HIDc 2048
#define Hc 16
#define DKc 128
#define DVc 128
#define Mc (Bc * Tc)            // 8192 rows

typedef unsigned long long ull;
typedef unsigned int u32;

// ------------------------- fp32 scratch (device globals) -------------------
__device__ float g_q   [(size_t)Mc * HIDc];
__device__ float g_k   [(size_t)Mc * HIDc];
__device__ float g_v   [(size_t)Mc * HIDc];
__device__ float g_eg  [(size_t)Mc * HIDc];   // exp(gate)
__device__ float g_sigf[(size_t)Mc * HIDc];   // sigmoid(factor)
__device__ float g_o   [(size_t)Mc * HIDc];
__device__ float g_beta[(size_t)Mc * Hc];

#define ID_Q    0
#define ID_K    1
#define ID_V    2
#define ID_EG   3
#define ID_SIGF 4
#define ID_O    5
#define ID_BETA 6

__device__ __forceinline__ float* scratch_resolve(int id) {
    switch (id) {
        case ID_Q:    return g_q;
        case ID_K:    return g_k;
        case ID_V:    return g_v;
        case ID_EG:   return g_eg;
        case ID_SIGF: return g_sigf;
        case ID_O:    return g_o;
        default:      return g_beta;
    }
}

// ------------------------- fp16 split pool ---------------------------------
constexpr size_t OFF_HB_HI  = 0;
constexpr size_t OFF_HB_LO  = OFF_HB_HI  + (size_t)Mc * HIDc;
constexpr size_t OFF_WQ_HI  = OFF_HB_LO  + (size_t)Mc * HIDc;
constexpr size_t OFF_WK_HI  = OFF_WQ_HI  + (size_t)HIDc * HIDc;
constexpr size_t OFF_WV_HI  = OFF_WK_HI  + (size_t)HIDc * HIDc;
constexpr size_t OFF_WO_HI  = OFF_WV_HI  + (size_t)HIDc * HIDc;
constexpr size_t OFF_FW0_HI = OFF_WO_HI  + (size_t)HIDc * HIDc;
constexpr size_t OFF_GW0_HI = OFF_FW0_HI + (size_t)128 * HIDc;
constexpr size_t OFF_FW1_HI = OFF_GW0_HI + (size_t)128 * HIDc;
constexpr size_t OFF_GW1_HI = OFF_FW1_HI + (size_t)HIDc * 128;
constexpr size_t OFF_TMP_HI = OFF_GW1_HI + (size_t)HIDc * 128;
constexpr size_t OFF_TMP_LO = OFF_TMP_HI + (size_t)Mc * 128;
constexpr size_t OFF_TMP2_HI= OFF_TMP_LO + (size_t)Mc * 128;
constexpr size_t OFF_TMP2_LO= OFF_TMP2_HI+ (size_t)Mc * 128;
constexpr size_t OFF_OG_HI  = OFF_TMP2_LO+ (size_t)Mc * 128;
constexpr size_t OFF_OG_LO  = OFF_OG_HI  + (size_t)Mc * HIDc;
constexpr size_t HF_TOTAL   = OFF_OG_LO  + (size_t)Mc * HIDc;

__device__ __half g_hfpool[HF_TOTAL];

// ------------------------------ f32x2 helpers ------------------------------
__device__ __forceinline__ ull f2pack(float a, float b) {
    ull r; asm("mov.b64 %0, {%1, %2};" : "=l"(r) : "f"(a), "f"(b)); return r;
}
__device__ __forceinline__ float2 f2unpack(ull x) {
    float2 r; asm("mov.b64 {%0, %1}, %2;" : "=f"(r.x), "=f"(r.y) : "l"(x)); return r;
}
__device__ __forceinline__ ull ffma2(ull a, ull b, ull c) {
    ull d; asm("fma.rn.f32x2 %0, %1, %2, %3;" : "=l"(d) : "l"(a), "l"(b), "l"(c)); return d;
}
__device__ __forceinline__ ull fmul2(ull a, ull b) {
    ull d; asm("mul.rn.f32x2 %0, %1, %2;" : "=l"(d) : "l"(a), "l"(b)); return d;
}
__device__ __forceinline__ ull fadd2(ull a, ull b) {
    ull d; asm("add.rn.f32x2 %0, %1, %2;" : "=l"(d) : "l"(a), "l"(b)); return d;
}

// ------------------------------ async copy ---------------------------------
__device__ __forceinline__ void cp16(void* s, const void* g) {
    u32 sa = (u32)__cvta_generic_to_shared(s);
    asm volatile("cp.async.ca.shared.global [%0], [%1], 16;" :: "r"(sa), "l"(g));
}
__device__ __forceinline__ void cp16u(u32 s, const void* g) {
    asm volatile("cp.async.cg.shared.global [%0], [%1], 16;" :: "r"(s), "l"(g));
}
__device__ __forceinline__ void cp4(void* s, const void* g) {
    u32 sa = (u32)__cvta_generic_to_shared(s);
    asm volatile("cp.async.ca.shared.global [%0], [%1], 4;" :: "r"(sa), "l"(g));
}
__device__ __forceinline__ void cp_commit() { asm volatile("cp.async.commit_group;"); }

__device__ __forceinline__ u32 smem_u32(const void* p) {
    return (u32)__cvta_generic_to_shared(p);
}

// ------------------------------ mma helpers --------------------------------
__device__ __forceinline__ void mma16816(float* c, const u32* a, const u32* b) {
    asm volatile(
        "mma.sync.aligned.m16n8k16.row.col.f32.f16.f16.f32 "
        "{%0,%1,%2,%3}, {%4,%5,%6,%7}, {%8,%9}, {%0,%1,%2,%3};"
        : "+f"(c[0]), "+f"(c[1]), "+f"(c[2]), "+f"(c[3])
        : "r"(a[0]), "r"(a[1]), "r"(a[2]), "r"(a[3]), "r"(b[0]), "r"(b[1]));
}
__device__ __forceinline__ void ldsm4(u32* r, u32 addr) {
    asm volatile("ldmatrix.sync.aligned.m8n8.x4.shared.b16 {%0,%1,%2,%3}, [%4];"
        : "=r"(r[0]), "=r"(r[1]), "=r"(r[2]), "=r"(r[3]) : "r"(addr));
}

// ------------------------------ split kernel -------------------------------
// x -> hi = fp16(x), lo = fp16(x - hi). lo optional (off_lo == 0 -> skip).
__global__ __launch_bounds__(256) void split_kernel(
    const float* __restrict__ src, size_t off_hi, size_t off_lo)
{
    size_t i = ((size_t)blockIdx.x * 256 + threadIdx.x) * 4;
    float4 x = *(const float4*)(src + i);
    __half h0 = __float2half_rn(x.x), h1 = __float2half_rn(x.y);
    __half h2 = __float2half_rn(x.z), h3 = __float2half_rn(x.w);
    uint2 ph;
    ph.x = (u32)__half_as_ushort(h0) | ((u32)__half_as_ushort(h1) << 16);
    ph.y = (u32)__half_as_ushort(h2) | ((u32)__half_as_ushort(h3) << 16);
    *(uint2*)(g_hfpool + off_hi + i) = ph;
    if (off_lo) {
        __half l0 = __float2half_rn(x.x - __half2float(h0));
        __half l1 = __float2half_rn(x.y - __half2float(h1));
        __half l2 = __float2half_rn(x.z - __half2float(h2));
        __half l3 = __float2half_rn(x.w - __half2float(h3));
        uint2 pl;
        pl.x = (u32)__half_as_ushort(l0) | ((u32)__half_as_ushort(l1) << 16);
        pl.y = (u32)__half_as_ushort(l2) | ((u32)__half_as_ushort(l3) << 16);
        *(uint2*)(g_hfpool + off_lo + i) = pl;
    }
}

// ------------------------- mma.sync fp16 GEMM ------------------------------
// C[M,N] = act( A[M,K] @ W[N,K]^T ), A split hi/lo, W fp16-hi:
//   D += Ahi*Whi + Alo*Whi   (fp32 accumulators)
// CTA tile 128x128, 256 thr (8 warps, 2x4; warp tile 64x32), BK=32, 3-stage
// cp.async pipeline (ONE barrier per chunk), XOR-swizzled smem, ldmatrix.
// ACT: 0 none | 1 silu | 2 kda-gate->exp | 3 sigmoid(x+aux1[n])
//      | 4 silu + per-head-row l2norm * sscale (requires head-aligned tiles)
// Output: Cid>=0 scratch fp32 | Cid==-1 Cext fp32 | Cid==-2 fp16 hi/lo pool.
constexpr int BKg         = 32;
constexpr int TILE_BYTES  = 128 * BKg * 2;     // 8 KB
constexpr int STAGE_BYTES = 3 * TILE_BYTES;    // 24 KB (Ahi, Alo, Whi)
constexpr int GSMEM       = 3 * STAGE_BYTES;   // 72 KB

template <int ACT>
__global__ __launch_bounds__(256) void mma_gemm(
    size_t a_hi, size_t a_lo, size_t w_hi,
    float* __restrict__ Cext, int Cid, int Ntot, int Ktot,
    const float* __restrict__ aux1, const float* __restrict__ aux2,
    float sscale, size_t o_hi, size_t o_lo)
{
    extern __shared__ char dsm[];
    const u32 sb = smem_u32(dsm);
    const int tid = threadIdx.x, lane = tid & 31, wid = tid >> 5;
    const int warp_m = wid & 1, warp_n = wid >> 1;    // 2 x 4 warp grid
    const int bm = blockIdx.y, bn = blockIdx.x;

    const __half* srcs[3] = {
        g_hfpool + a_hi + (size_t)bm * 128 * Ktot,
        g_hfpool + a_lo + (size_t)bm * 128 * Ktot,
        g_hfpool + w_hi + (size_t)bn * 128 * Ktot };

    float acc[4][4][4];
#pragma unroll
    for (int i = 0; i < 4; i++)
#pragma unroll
        for (int j = 0; j < 4; j++)
#pragma unroll
            for (int e = 0; e < 4; e++) acc[i][j][e] = 0.f;

    const int NC = Ktot / BKg;
    const int jq = lane >> 3, rq = lane & 7;
    const int jlow = jq & 1, jhi = jq >> 1;

    // --- stage loader: 3 tiles x 128 rows x 4 x 16B groups, swizzled
    auto load_stage = [&](int stage, int c) {
        u32 base = sb + (u32)stage * STAGE_BYTES;
#pragma unroll
        for (int t = 0; t < 3; t++) {
            const __half* src = srcs[t] + (size_t)c * BKg;
            u32 tb = base + (u32)t * TILE_BYTES;
#pragma unroll
            for (int i = 0; i < 2; i++) {
                int idx = tid + i * 256;                 // 0..511
                u32 row = (u32)(idx >> 2), g = (u32)(idx & 3);
                u32 so = tb + row * 64u + ((g ^ (row & 3u)) * 16u);
                cp16u(so, (const char*)(src + (size_t)row * Ktot) + g * 16);
            }
        }
    };

    load_stage(0, 0); cp_commit();
    load_stage(1, 1); cp_commit();

    int s_cur = 0, s_pre = 2;     // compute stage; prefetch stage (c+2)%3
    for (int c = 0; c < NC; c++) {
        if (c == NC - 1) {
            asm volatile("cp.async.wait_group 0;" ::: "memory");
        } else {
            asm volatile("cp.async.wait_group 1;" ::: "memory");
        }
        __syncthreads();
        // prefetch AFTER barrier: stage s_pre == (c-1)%3, whose readers are
        // provably done (their compute preceded this barrier).
        if (c + 2 < NC) {
            load_stage(s_pre, c + 2); cp_commit();
        }

        const u32 base = sb + (u32)s_cur * STAGE_BYTES;
        const u32 ah = base, al = base + TILE_BYTES;
        const u32 wh = base + 2 * TILE_BYTES;

#pragma unroll
        for (int ks = 0; ks < 2; ks++) {
            const u32 g = (u32)(ks * 2 + jhi);
            u32 a_hi_f[4][4], a_lo_f[4][4];
#pragma unroll
            for (int mi = 0; mi < 4; mi++) {
                u32 row = (u32)(warp_m * 64 + mi * 16 + jlow * 8 + rq);
                u32 off = row * 64u + ((g ^ (row & 3u)) * 16u);
                ldsm4(a_hi_f[mi], ah + off);
                ldsm4(a_lo_f[mi], al + off);
            }
            u32 b_hi_f[4][2];
#pragma unroll
            for (int pi = 0; pi < 2; pi++) {
                u32 row = (u32)(warp_n * 32 + pi * 16 + jlow * 8 + rq);
                u32 off = row * 64u + ((g ^ (row & 3u)) * 16u);
                u32 t0[4];
                ldsm4(t0, wh + off);
                b_hi_f[2*pi][0] = t0[0]; b_hi_f[2*pi][1] = t0[2];
                b_hi_f[2*pi+1][0] = t0[1]; b_hi_f[2*pi+1][1] = t0[3];
            }
#pragma unroll
            for (int mi = 0; mi < 4; mi++)
#pragma unroll
                for (int ni = 0; ni < 4; ni++) {
                    mma16816(acc[mi][ni], a_hi_f[mi], b_hi_f[ni]);
                    mma16816(acc[mi][ni], a_lo_f[mi], b_hi_f[ni]);
                }
        }
        s_cur = (s_cur == 2) ? 0 : s_cur + 1;
        s_pre = (s_pre == 2) ? 0 : s_pre + 1;
    }

    // ---------------- epilogue ----------------
    const int qrow = lane >> 2, qcol = (lane & 3) * 2;
    const int n_warp0 = bn * 128 + warp_n * 32;

    if (ACT == 4) {
        // silu + per-head-row l2norm * sscale. Tile is head-aligned (128 cols
        // = one head). Transform acc to silu in place, reduce sum-of-squares
        // per row across the 4 warp_n groups via smem.
        __syncthreads();                      // stage buffers now reusable
        float* red = (float*)dsm;             // [128 rows][4 warp_n]
#pragma unroll
        for (int mi = 0; mi < 4; mi++)
#pragma unroll
            for (int half = 0; half < 2; half++) {
                float ss = 0.f;
#pragma unroll
                for (int ni = 0; ni < 4; ni++) {
#pragma unroll
                    for (int e = 0; e < 2; e++) {
                        float x = acc[mi][ni][half * 2 + e];
                        x = x / (1.0f + expf(-x));
                        acc[mi][ni][half * 2 + e] = x;
                        ss += x * x;
                    }
                }
                ss += __shfl_xor_sync(0xffffffffu, ss, 1);
                ss += __shfl_xor_sync(0xffffffffu, ss, 2);
                if ((lane & 3) == 0) {
                    int rowl = warp_m * 64 + mi * 16 + half * 8 + qrow;
                    red[rowl * 4 + warp_n] = ss;
                }
            }
        __syncthreads();
        float* C = scratch_resolve(Cid);
#pragma unroll
        for (int mi = 0; mi < 4; mi++)
#pragma unroll
            for (int half = 0; half < 2; half++) {
                int rowl = warp_m * 64 + mi * 16 + half * 8 + qrow;
                float tot = red[rowl * 4] + red[rowl * 4 + 1]
                          + red[rowl * 4 + 2] + red[rowl * 4 + 3];
                float r = rsqrtf(tot + 1e-6f) * sscale;
                const int m = bm * 128 + rowl;
                float* crow = C + (size_t)m * Ntot + n_warp0;
#pragma unroll
                for (int ni = 0; ni < 4; ni++) {
                    float2 o2;
                    o2.x = acc[mi][ni][half * 2]     * r;
                    o2.y = acc[mi][ni][half * 2 + 1] * r;
                    *(float2*)(crow + ni * 8 + qcol) = o2;
                }
            }
        return;
    }

    float* C = (Cid >= 0) ? scratch_resolve(Cid) : Cext;
#pragma unroll
    for (int mi = 0; mi < 4; mi++) {
#pragma unroll
        for (int half = 0; half < 2; half++) {
            const int m = bm * 128 + warp_m * 64 + mi * 16 + half * 8 + qrow;
#pragma unroll
            for (int ni = 0; ni < 4; ni++) {
                float x0 = acc[mi][ni][half * 2];
                float x1 = acc[mi][ni][half * 2 + 1];
                const int n = n_warp0 + ni * 8 + qcol;
                if (ACT == 1) {
                    x0 = x0 / (1.0f + expf(-x0));
                    x1 = x1 / (1.0f + expf(-x1));
                } else if (ACT == 2) {
                    float a0 = expf(aux1[n >> 7]);
                    float a1 = expf(aux1[(n + 1) >> 7]);
                    float s0 = x0 + aux2[n], s1 = x1 + aux2[n + 1];
                    s0 = (s0 > 20.0f) ? s0 : log1pf(expf(s0));
                    s1 = (s1 > 20.0f) ? s1 : log1pf(expf(s1));
                    x0 = expf(-a0 * s0); x1 = expf(-a1 * s1);
                } else if (ACT == 3) {
                    x0 = 1.0f / (1.0f + expf(-(x0 + aux1[n])));
                    x1 = 1.0f / (1.0f + expf(-(x1 + aux1[n + 1])));
                }
                if (Cid == -2) {
                    // fp16 hi/lo direct emit
                    __half h0 = __float2half_rn(x0), h1 = __float2half_rn(x1);
                    __half l0 = __float2half_rn(x0 - __half2float(h0));
                    __half l1 = __float2half_rn(x1 - __half2float(h1));
                    size_t base = (size_t)m * Ntot + n;
                    *(u32*)(g_hfpool + o_hi + base) =
                        (u32)__half_as_ushort(h0) | ((u32)__half_as_ushort(h1) << 16);
                    *(u32*)(g_hfpool + o_lo + base) =
                        (u32)__half_as_ushort(l0) | ((u32)__half_as_ushort(l1) << 16);
                } else {
                    float2 o2; o2.x = x0; o2.y = x1;
                    *(float2*)(C + (size_t)m * Ntot + n) = o2;
                }
            }
        }
    }
}

// --------------------------- beta = sigmoid(h @ b_w^T) ---------------------
__global__ __launch_bounds__(512) void beta_kernel(
    const float* __restrict__ H, const float* __restrict__ BW)
{
    float* BETA = scratch_resolve(ID_BETA);
    const int m = blockIdx.x;
    const int w = threadIdx.x >> 5, lane = threadIdx.x & 31;
    const float4* hr = (const float4*)(H + (size_t)m * HIDc);
    const float4* br = (const float4*)(BW + (size_t)w * HIDc);
    float s = 0.f;
#pragma unroll 4
    for (int i = lane; i < HIDc / 4; i += 32) {
        float4 a = hr[i], b = br[i];
        s += a.x * b.x + a.y * b.y + a.z * b.z + a.w * b.w;
    }
#pragma unroll
    for (int off = 16; off > 0; off >>= 1)
        s += __shfl_xor_sync(0xffffffffu, s, off);
    if (lane == 0) BETA[(size_t)m * Hc + w] = 1.0f / (1.0f + expf(-s));
}

// ---------- gated RMS norm: og = rms(o)*w*sigf, emitted as fp16 hi/lo ------
__global__ __launch_bounds__(128) void gate_kernel(const float* __restrict__ NW)
{
    const float* O    = scratch_resolve(ID_O);
    const float* SIGF = scratch_resolve(ID_SIGF);
    const int h = blockIdx.x, m = blockIdx.y;
    const int v = threadIdx.x;
    const size_t off = (size_t)m * HIDc + (size_t)h * DVc + v;
    float x = O[off];
    float s = x * x;
#pragma unroll
    for (int o = 16; o > 0; o >>= 1) s += __shfl_xor_sync(0xffffffffu, s, o);
    __shared__ float red[4];
    if ((v & 31) == 0) red[v >> 5] = s;
    __syncthreads();
    float tot = red[0] + red[1] + red[2] + red[3];
    float r = rsqrtf(tot * (1.0f / DVc) + 1e-5f);
    float y = x * r * NW[v] * SIGF[off];
    __half hi = __float2half_rn(y);
    __half lo = __float2half_rn(y - __half2float(hi));
    g_hfpool[OFF_OG_HI + off] = hi;
    g_hfpool[OFF_OG_LO + off] = lo;
}

// ------------------------------ recurrent scan -----------------------------
// grid (2, H, B); 256 threads. CTA owns 64 v-cols; 4 threads split the 128-k
// dim (kq = tid&3, 32 k each, 16 state pairs/thread). 4 smem stages, prefetch
// distance 2 -> single barrier per step. Rows skewed +4 floats per 32-block.
#define SROW 144
#define SKW(i) ((i) + ((((u32)(i)) >> 5) << 2))

__global__ __launch_bounds__(256) void scan_kernel(
    const float* __restrict__ S0,
    float* __restrict__ Sout, int writeS)
{
    const float* Q    = scratch_resolve(ID_Q);
    const float* K    = scratch_resolve(ID_K);
    const float* V    = scratch_resolve(ID_V);
    const float* EG   = scratch_resolve(ID_EG);
    const float* BETA = scratch_resolve(ID_BETA);
    float*       O    = scratch_resolve(ID_O);

    const int vh = blockIdx.x, h = blockIdx.y, b = blockIdx.z;
    const int tid = threadIdx.x;
    const int vloc = tid >> 2, kq = tid & 3;
    const int v = vh * 64 + vloc;
    const int ks = kq * 32;

    __shared__ float sbuf[4][4][SROW];   // [stage][k,q,v,eg][128 skewed]
    __shared__ float sbeta[4];

    const size_t rowbase = (size_t)b * Tc * HIDc + (size_t)h * DKc;

    ull S[16];
    {
        const float* s0p = S0 + (((size_t)(b * Hc + h) * DKc + ks) * DVc + v);
#pragma unroll
        for (int j2 = 0; j2 < 16; j2++)
            S[j2] = f2pack(s0p[(size_t)(2 * j2) * DVc], s0p[(size_t)(2 * j2 + 1) * DVc]);
    }

    const int grp = tid >> 6, idx = tid & 63;
    const float* srcs[4] = {K, Q, V, EG};

#pragma unroll
    for (int t = 0; t < 2; t++) {
        if (idx < 32)
            cp16(&sbuf[t][grp][idx * 4 + ((idx >> 3) << 2)],
                 srcs[grp] + rowbase + (size_t)t * HIDc + idx * 4);
        if (tid == 0) cp4(&sbeta[t], BETA + ((size_t)(b * Tc + t)) * Hc + h);
        cp_commit();
    }

    for (int t = 0; t < Tc; t++) {
        if (t + 2 < Tc) {
            const int st = (t + 2) & 3;
            if (idx < 32)
                cp16(&sbuf[st][grp][idx * 4 + ((idx >> 3) << 2)],
                     srcs[grp] + rowbase + (size_t)(t + 2) * HIDc + idx * 4);
            if (tid == 0) cp4(&sbeta[st], BETA + ((size_t)(b * Tc + t + 2)) * Hc + h);
            cp_commit();
            asm volatile("cp.async.wait_group 2;" ::: "memory");
        } else {
            asm volatile("cp.async.wait_group 0;" ::: "memory");
        }
        __syncthreads();

        const int cb = t & 3;
        const float beta = sbeta[cb];
        const float vv = sbuf[cb][2][SKW(v)];
        const int kb = ks + kq * 4;        // skewed base for this k-quarter

        ull k2[16];
        ull kva = 0ull, kvb = 0ull;
#pragma unroll
        for (int j2 = 0; j2 < 16; j2 += 2) {
            k2[j2]     = *(const ull*)&sbuf[cb][0][kb + 2 * j2];
            k2[j2 + 1] = *(const ull*)&sbuf[cb][0][kb + 2 * j2 + 2];
            ull e0 = *(const ull*)&sbuf[cb][3][kb + 2 * j2];
            ull e1 = *(const ull*)&sbuf[cb][3][kb + 2 * j2 + 2];
            S[j2]     = fmul2(S[j2],     e0);
            S[j2 + 1] = fmul2(S[j2 + 1], e1);
            kva = ffma2(k2[j2],     S[j2],     kva);
            kvb = ffma2(k2[j2 + 1], S[j2 + 1], kvb);
        }
        ull kv2 = fadd2(kva, kvb);
        float2 kvp = f2unpack(kv2);
        float kv = kvp.x + kvp.y;
        kv += __shfl_xor_sync(0xffffffffu, kv, 1);
        kv += __shfl_xor_sync(0xffffffffu, kv, 2);

        const float delta = (vv - kv) * beta;
        const ull d2 = f2pack(delta, delta);

        ull oa = 0ull, ob = 0ull;
#pragma unroll
        for (int j2 = 0; j2 < 16; j2 += 2) {
            S[j2]     = ffma2(k2[j2],     d2, S[j2]);
            S[j2 + 1] = ffma2(k2[j2 + 1], d2, S[j2 + 1]);
            ull q0 = *(const ull*)&sbuf[cb][1][kb + 2 * j2];
            ull q1 = *(const ull*)&sbuf[cb][1][kb + 2 * j2 + 2];
            oa = ffma2(q0, S[j2],     oa);
            ob = ffma2(q1, S[j2 + 1], ob);
        }
        ull o2 = fadd2(oa, ob);
        float2 op = f2unpack(o2);
        float o = op.x + op.y;
        o += __shfl_xor_sync(0xffffffffu, o, 1);
        o += __shfl_xor_sync(0xffffffffu, o, 2);
        if (kq == 0)
            O[rowbase + (size_t)t * HIDc + v] = o;
    }

    if (writeS) {
        float* sp = Sout + (((size_t)(b * Hc + h) * DKc + ks) * DVc + v);
#pragma unroll
        for (int j2 = 0; j2 < 16; j2++) {
            float2 c = f2unpack(S[j2]);
            sp[(size_t)(2 * j2) * DVc]     = c.x;
            sp[(size_t)(2 * j2 + 1) * DVc] = c.y;
        }
    }
}

// ------------------------------ host launcher ------------------------------
extern "C" void kernel_launch(void* const* d_in, const int* in_sizes, int n_in,
                              void* d_out, int out_size)
{
    const float* h      = (const float*)d_in[0];
    const float* S0     = (const float*)d_in[1];
    const float* q_w    = (const float*)d_in[2];
    const float* k_w    = (const float*)d_in[3];
    const float* v_w    = (const float*)d_in[4];
    const float* f_w0   = (const float*)d_in[5];
    const float* f_w1   = (const float*)d_in[6];
    const float* b_w    = (const float*)d_in[7];
    const float* A_log  = (const float*)d_in[8];
    const float* dt_b   = (const float*)d_in[9];
    const float* g_w0   = (const float*)d_in[10];
    const float* g_w1   = (const float*)d_in[11];
    const float* g_b1   = (const float*)d_in[12];
    const float* o_nw   = (const float*)d_in[13];
    const float* o_w    = (const float*)d_in[14];
    float* out = (float*)d_out;

    cudaFuncSetAttribute(mma_gemm<0>, cudaFuncAttributeMaxDynamicSharedMemorySize, GSMEM);
    cudaFuncSetAttribute(mma_gemm<1>, cudaFuncAttributeMaxDynamicSharedMemorySize, GSMEM);
    cudaFuncSetAttribute(mma_gemm<2>, cudaFuncAttributeMaxDynamicSharedMemorySize, GSMEM);
    cudaFuncSetAttribute(mma_gemm<3>, cudaFuncAttributeMaxDynamicSharedMemorySize, GSMEM);
    cudaFuncSetAttribute(mma_gemm<4>, cudaFuncAttributeMaxDynamicSharedMemorySize, GSMEM);

    const dim3 g_big(HIDc / 128, Mc / 128);   // (16, 64)
    const dim3 g_n128(1, Mc / 128);           // (1, 64)

    // ---- split inputs into fp16 (A operands hi+lo; weights hi only) ----
    split_kernel<<<(Mc * HIDc) / 1024, 256>>>(h,    OFF_HB_HI,  OFF_HB_LO);
    split_kernel<<<(HIDc * HIDc) / 1024, 256>>>(q_w, OFF_WQ_HI,  0);
    split_kernel<<<(HIDc * HIDc) / 1024, 256>>>(k_w, OFF_WK_HI,  0);
    split_kernel<<<(HIDc * HIDc) / 1024, 256>>>(v_w, OFF_WV_HI,  0);
    split_kernel<<<(HIDc * HIDc) / 1024, 256>>>(o_w, OFF_WO_HI,  0);
    split_kernel<<<(128 * HIDc) / 1024, 256>>>(f_w0, OFF_FW0_HI, 0);
    split_kernel<<<(128 * HIDc) / 1024, 256>>>(g_w0, OFF_GW0_HI, 0);
    split_kernel<<<(HIDc * 128) / 1024, 256>>>(f_w1, OFF_FW1_HI, 0);
    split_kernel<<<(HIDc * 128) / 1024, 256>>>(g_w1, OFF_GW1_HI, 0);

    // ---- q,k projections: silu + fused l2norm (scale folds 1/sqrt(DK)) ----
    mma_gemm<4><<<g_big, 256, GSMEM>>>(OFF_HB_HI, OFF_HB_LO, OFF_WQ_HI,
                                       nullptr, ID_Q, HIDc, HIDc, nullptr, nullptr,
                                       0.08838834764831845f, 0, 0);
    mma_gemm<4><<<g_big, 256, GSMEM>>>(OFF_HB_HI, OFF_HB_LO, OFF_WK_HI,
                                       nullptr, ID_K, HIDc, HIDc, nullptr, nullptr,
                                       1.0f, 0, 0);
    // ---- v projection: silu only ----
    mma_gemm<1><<<g_big, 256, GSMEM>>>(OFF_HB_HI, OFF_HB_LO, OFF_WV_HI,
                                       nullptr, ID_V, HIDc, HIDc, nullptr, nullptr,
                                       0.f, 0, 0);

    // ---- gate path: tmp = h@f_w0^T (direct fp16 hi/lo emit) ----
    mma_gemm<0><<<g_n128, 256, GSMEM>>>(OFF_HB_HI, OFF_HB_LO, OFF_FW0_HI,
                                        nullptr, -2, 128, HIDc, nullptr, nullptr,
                                        0.f, OFF_TMP_HI, OFF_TMP_LO);
    mma_gemm<2><<<g_big, 256, GSMEM>>>(OFF_TMP_HI, OFF_TMP_LO, OFF_FW1_HI,
                                       nullptr, ID_EG, HIDc, 128, A_log, dt_b,
                                       0.f, 0, 0);

    // ---- beta ----
    beta_kernel<<<Mc, 512>>>(h, b_w);

    // ---- output gate factor path ----
    mma_gemm<0><<<g_n128, 256, GSMEM>>>(OFF_HB_HI, OFF_HB_LO, OFF_GW0_HI,
                                        nullptr, -2, 128, HIDc, nullptr, nullptr,
                                        0.f, OFF_TMP2_HI, OFF_TMP2_LO);
    mma_gemm<3><<<g_big, 256, GSMEM>>>(OFF_TMP2_HI, OFF_TMP2_LO, OFF_GW1_HI,
                                       nullptr, ID_SIGF, HIDc, 128, g_b1, nullptr,
                                       0.f, 0, 0);

    // ---- recurrent scan ----
    const size_t out_elems = (size_t)Mc * HIDc;                 // 16,777,216
    const size_t s_elems   = (size_t)Bc * Hc * DKc * DVc;       //  1,048,576
    const int writeS = ((size_t)out_size >= out_elems + s_elems) ? 1 : 0;
    scan_kernel<<<dim3(2, Hc, Bc), 256>>>(S0, out + out_elems, writeS);

    // ---- gated rms norm (emits fp16 hi/lo) + final projection ----
    gate_kernel<<<dim3(Hc, Mc), 128>>>(o_nw);
    mma_gemm<0><<<g_big, 256, GSMEM>>>(OFF_OG_HI, OFF_OG_LO, OFF_WO_HI,
                                       out, -1, HIDc, HIDc, nullptr, nullptr,
                                       0.f, 0, 0);
}

// round 14
// speedup vs baseline: 1.3434x; 1.0129x over previous
#include <cuda_runtime.h>
#include <cuda_fp16.h>
#include <cuda_bf16.h>
#include <cstdint>

// ---------------------------------------------------------------------------
// KimiDeltaAttention — mma.sync fp16 GEMMs (A hi/lo split, W fp16; 2 MMAs per
// product, fp32 accum; 3-stage pipeline, fused l2norm epilogue, merged qkv)
// + fp32 scan. B=4, T=2048, HID=2048, H=16, DK=DV=128
// compute_103 PTX only (no 'a' features): tensor path = mma.sync m16n8k16 f16.
// ---------------------------------------------------------------------------

#define Bc 4
#define Tc 2048
#define HIDc 2048
#define Hc 16
#define DKc 128
#define DVc 128
#define Mc (Bc * Tc)            // 8192 rows

typedef unsigned long long ull;
typedef unsigned int u32;

// ------------------------- fp32 scratch (device globals) -------------------
__device__ float g_q   [(size_t)Mc * HIDc];
__device__ float g_k   [(size_t)Mc * HIDc];
__device__ float g_v   [(size_t)Mc * HIDc];
__device__ float g_eg  [(size_t)Mc * HIDc];   // exp(gate)
__device__ float g_sigf[(size_t)Mc * HIDc];   // sigmoid(factor)
__device__ float g_o   [(size_t)Mc * HIDc];
__device__ float g_beta[(size_t)Mc * Hc];

#define ID_Q    0
#define ID_K    1
#define ID_V    2
#define ID_EG   3
#define ID_SIGF 4
#define ID_O    5
#define ID_BETA 6

__device__ __forceinline__ float* scratch_resolve(int id) {
    switch (id) {
        case ID_Q:    return g_q;
        case ID_K:    return g_k;
        case ID_V:    return g_v;
        case ID_EG:   return g_eg;
        case ID_SIGF: return g_sigf;
        case ID_O:    return g_o;
        default:      return g_beta;
    }
}

// ------------------------- fp16 split pool ---------------------------------
constexpr size_t BS_W       = (size_t)HIDc * HIDc;
constexpr size_t OFF_HB_HI  = 0;
constexpr size_t OFF_HB_LO  = OFF_HB_HI  + (size_t)Mc * HIDc;
constexpr size_t OFF_WQ_HI  = OFF_HB_LO  + (size_t)Mc * HIDc;   // WQ,WK,WV consecutive
constexpr size_t OFF_WK_HI  = OFF_WQ_HI  + BS_W;
constexpr size_t OFF_WV_HI  = OFF_WK_HI  + BS_W;
constexpr size_t OFF_WO_HI  = OFF_WV_HI  + BS_W;
constexpr size_t OFF_FW0_HI = OFF_WO_HI  + BS_W;
constexpr size_t OFF_GW0_HI = OFF_FW0_HI + (size_t)128 * HIDc;
constexpr size_t OFF_FW1_HI = OFF_GW0_HI + (size_t)128 * HIDc;
constexpr size_t OFF_GW1_HI = OFF_FW1_HI + (size_t)HIDc * 128;
constexpr size_t OFF_TMP_HI = OFF_GW1_HI + (size_t)HIDc * 128;
constexpr size_t OFF_TMP_LO = OFF_TMP_HI + (size_t)Mc * 128;
constexpr size_t OFF_TMP2_HI= OFF_TMP_LO + (size_t)Mc * 128;
constexpr size_t OFF_TMP2_LO= OFF_TMP2_HI+ (size_t)Mc * 128;
constexpr size_t OFF_OG_HI  = OFF_TMP2_LO+ (size_t)Mc * 128;
constexpr size_t OFF_OG_LO  = OFF_OG_HI  + (size_t)Mc * HIDc;
constexpr size_t HF_TOTAL   = OFF_OG_LO  + (size_t)Mc * HIDc;

__device__ __half g_hfpool[HF_TOTAL];

// ------------------------------ f32x2 helpers ------------------------------
__device__ __forceinline__ ull f2pack(float a, float b) {
    ull r; asm("mov.b64 %0, {%1, %2};" : "=l"(r) : "f"(a), "f"(b)); return r;
}
__device__ __forceinline__ float2 f2unpack(ull x) {
    float2 r; asm("mov.b64 {%0, %1}, %2;" : "=f"(r.x), "=f"(r.y) : "l"(x)); return r;
}
__device__ __forceinline__ ull ffma2(ull a, ull b, ull c) {
    ull d; asm("fma.rn.f32x2 %0, %1, %2, %3;" : "=l"(d) : "l"(a), "l"(b), "l"(c)); return d;
}
__device__ __forceinline__ ull fmul2(ull a, ull b) {
    ull d; asm("mul.rn.f32x2 %0, %1, %2;" : "=l"(d) : "l"(a), "l"(b)); return d;
}
__device__ __forceinline__ ull fadd2(ull a, ull b) {
    ull d; asm("add.rn.f32x2 %0, %1, %2;" : "=l"(d) : "l"(a), "l"(b)); return d;
}

// ------------------------------ async copy ---------------------------------
__device__ __forceinline__ void cp16(void* s, const void* g) {
    u32 sa = (u32)__cvta_generic_to_shared(s);
    asm volatile("cp.async.ca.shared.global [%0], [%1], 16;" :: "r"(sa), "l"(g));
}
__device__ __forceinline__ void cp16u(u32 s, const void* g) {
    asm volatile("cp.async.cg.shared.global [%0], [%1], 16;" :: "r"(s), "l"(g));
}
__device__ __forceinline__ void cp4(void* s, const void* g) {
    u32 sa = (u32)__cvta_generic_to_shared(s);
    asm volatile("cp.async.ca.shared.global [%0], [%1], 4;" :: "r"(sa), "l"(g));
}
__device__ __forceinline__ void cp_commit() { asm volatile("cp.async.commit_group;"); }

__device__ __forceinline__ u32 smem_u32(const void* p) {
    return (u32)__cvta_generic_to_shared(p);
}

// ------------------------------ mma helpers --------------------------------
__device__ __forceinline__ void mma16816(float* c, const u32* a, const u32* b) {
    asm volatile(
        "mma.sync.aligned.m16n8k16.row.col.f32.f16.f16.f32 "
        "{%0,%1,%2,%3}, {%4,%5,%6,%7}, {%8,%9}, {%0,%1,%2,%3};"
        : "+f"(c[0]), "+f"(c[1]), "+f"(c[2]), "+f"(c[3])
        : "r"(a[0]), "r"(a[1]), "r"(a[2]), "r"(a[3]), "r"(b[0]), "r"(b[1]));
}
__device__ __forceinline__ void ldsm4(u32* r, u32 addr) {
    asm volatile("ldmatrix.sync.aligned.m8n8.x4.shared.b16 {%0,%1,%2,%3}, [%4];"
        : "=r"(r[0]), "=r"(r[1]), "=r"(r[2]), "=r"(r[3]) : "r"(addr));
}

// ------------------------------ merged split -------------------------------
// One launch converts ALL fp32 operands to fp16 (h: hi+lo, weights: hi only).
// Block->segment mapping uses compile-time cumulative block counts.
constexpr u32 NB_HB  = (u32)((size_t)Mc * HIDc / 1024);    // 16384
constexpr u32 NB_W   = (u32)(BS_W / 1024);                  //  4096
constexpr u32 NB_W0  = (u32)((size_t)128 * HIDc / 1024);    //   256
constexpr u32 CUM0 = NB_HB;                  // h
constexpr u32 CUM1 = CUM0 + NB_W;            // q_w
constexpr u32 CUM2 = CUM1 + NB_W;            // k_w
constexpr u32 CUM3 = CUM2 + NB_W;            // v_w
constexpr u32 CUM4 = CUM3 + NB_W;            // o_w
constexpr u32 CUM5 = CUM4 + NB_W0;           // f_w0
constexpr u32 CUM6 = CUM5 + NB_W0;           // g_w0
constexpr u32 CUM7 = CUM6 + NB_W0;           // f_w1
constexpr u32 CUM8 = CUM7 + NB_W0;           // g_w1  (total 33792)

__global__ __launch_bounds__(256) void split_all(
    const float* __restrict__ h,   const float* __restrict__ q_w,
    const float* __restrict__ k_w, const float* __restrict__ v_w,
    const float* __restrict__ o_w, const float* __restrict__ f_w0,
    const float* __restrict__ g_w0,const float* __restrict__ f_w1,
    const float* __restrict__ g_w1)
{
    const u32 b = blockIdx.x;
    const float* src; size_t off_hi; size_t off_lo = 0; u32 b0;
    if      (b < CUM0) { src = h;    off_hi = OFF_HB_HI;  off_lo = OFF_HB_LO; b0 = 0; }
    else if (b < CUM1) { src = q_w;  off_hi = OFF_WQ_HI;  b0 = CUM0; }
    else if (b < CUM2) { src = k_w;  off_hi = OFF_WK_HI;  b0 = CUM1; }
    else if (b < CUM3) { src = v_w;  off_hi = OFF_WV_HI;  b0 = CUM2; }
    else if (b < CUM4) { src = o_w;  off_hi = OFF_WO_HI;  b0 = CUM3; }
    else if (b < CUM5) { src = f_w0; off_hi = OFF_FW0_HI; b0 = CUM4; }
    else if (b < CUM6) { src = g_w0; off_hi = OFF_GW0_HI; b0 = CUM5; }
    else if (b < CUM7) { src = f_w1; off_hi = OFF_FW1_HI; b0 = CUM6; }
    else               { src = g_w1; off_hi = OFF_GW1_HI; b0 = CUM7; }

    size_t i = ((size_t)(b - b0) * 256 + threadIdx.x) * 4;
    float4 x = *(const float4*)(src + i);
    __half h0 = __float2half_rn(x.x), h1 = __float2half_rn(x.y);
    __half h2 = __float2half_rn(x.z), h3 = __float2half_rn(x.w);
    uint2 ph;
    ph.x = (u32)__half_as_ushort(h0) | ((u32)__half_as_ushort(h1) << 16);
    ph.y = (u32)__half_as_ushort(h2) | ((u32)__half_as_ushort(h3) << 16);
    *(uint2*)(g_hfpool + off_hi + i) = ph;
    if (off_lo) {
        __half l0 = __float2half_rn(x.x - __half2float(h0));
        __half l1 = __float2half_rn(x.y - __half2float(h1));
        __half l2 = __float2half_rn(x.z - __half2float(h2));
        __half l3 = __float2half_rn(x.w - __half2float(h3));
        uint2 pl;
        pl.x = (u32)__half_as_ushort(l0) | ((u32)__half_as_ushort(l1) << 16);
        pl.y = (u32)__half_as_ushort(l2) | ((u32)__half_as_ushort(l3) << 16);
        *(uint2*)(g_hfpool + off_lo + i) = pl;
    }
}

// ------------------------- mma.sync fp16 GEMM ------------------------------
// C[M,N] = act( A[M,K] @ W[N,K]^T ), A split hi/lo, W fp16-hi:
//   D += Ahi*Whi + Alo*Whi   (fp32 accumulators)
// CTA tile 128x128, 256 thr (8 warps, 2x4; warp tile 64x32), BK=32, 3-stage
// cp.async pipeline (ONE barrier per chunk), XOR-swizzled smem, ldmatrix.
// ACT: 0 none | 2 kda-gate->exp | 3 sigmoid(x+aux1[n])
//      | 5 merged qkv: z=0 silu+l2norm*0.0884, z=1 silu+l2norm, z=2 silu
// Output: Cid>=0 scratch fp32 | Cid==-1 Cext fp32 | Cid==-2 fp16 hi/lo pool.
// For ACT==5: weight block = w_hi + z*BS_W, dest id = Cid + z.
constexpr int BKg         = 32;
constexpr int TILE_BYTES  = 128 * BKg * 2;     // 8 KB
constexpr int STAGE_BYTES = 3 * TILE_BYTES;    // 24 KB (Ahi, Alo, Whi)
constexpr int GSMEM       = 3 * STAGE_BYTES;   // 72 KB

template <int ACT>
__global__ __launch_bounds__(256) void mma_gemm(
    size_t a_hi, size_t a_lo, size_t w_hi,
    float* __restrict__ Cext, int Cid, int Ntot, int Ktot,
    const float* __restrict__ aux1, const float* __restrict__ aux2,
    size_t o_hi, size_t o_lo)
{
    extern __shared__ char dsm[];
    const u32 sb = smem_u32(dsm);
    const int tid = threadIdx.x, lane = tid & 31, wid = tid >> 5;
    const int warp_m = wid & 1, warp_n = wid >> 1;    // 2 x 4 warp grid
    const int bm = blockIdx.y, bn = blockIdx.x, bz = blockIdx.z;

    const __half* srcs[3] = {
        g_hfpool + a_hi + (size_t)bm * 128 * Ktot,
        g_hfpool + a_lo + (size_t)bm * 128 * Ktot,
        g_hfpool + w_hi + (size_t)bz * BS_W + (size_t)bn * 128 * Ktot };

    float acc[4][4][4];
#pragma unroll
    for (int i = 0; i < 4; i++)
#pragma unroll
        for (int j = 0; j < 4; j++)
#pragma unroll
            for (int e = 0; e < 4; e++) acc[i][j][e] = 0.f;

    const int NC = Ktot / BKg;
    const int jq = lane >> 3, rq = lane & 7;
    const int jlow = jq & 1, jhi = jq >> 1;

    auto load_stage = [&](int stage, int c) {
        u32 base = sb + (u32)stage * STAGE_BYTES;
#pragma unroll
        for (int t = 0; t < 3; t++) {
            const __half* src = srcs[t] + (size_t)c * BKg;
            u32 tb = base + (u32)t * TILE_BYTES;
#pragma unroll
            for (int i = 0; i < 2; i++) {
                int idx = tid + i * 256;                 // 0..511
                u32 row = (u32)(idx >> 2), g = (u32)(idx & 3);
                u32 so = tb + row * 64u + ((g ^ (row & 3u)) * 16u);
                cp16u(so, (const char*)(src + (size_t)row * Ktot) + g * 16);
            }
        }
    };

    load_stage(0, 0); cp_commit();
    load_stage(1, 1); cp_commit();

    int s_cur = 0, s_pre = 2;     // compute stage; prefetch stage (c+2)%3
    for (int c = 0; c < NC; c++) {
        if (c == NC - 1) {
            asm volatile("cp.async.wait_group 0;" ::: "memory");
        } else {
            asm volatile("cp.async.wait_group 1;" ::: "memory");
        }
        __syncthreads();
        // prefetch AFTER barrier: stage s_pre == (c-1)%3, readers provably done.
        if (c + 2 < NC) {
            load_stage(s_pre, c + 2); cp_commit();
        }

        const u32 base = sb + (u32)s_cur * STAGE_BYTES;
        const u32 ah = base, al = base + TILE_BYTES;
        const u32 wh = base + 2 * TILE_BYTES;

#pragma unroll
        for (int ks = 0; ks < 2; ks++) {
            const u32 g = (u32)(ks * 2 + jhi);
            u32 a_hi_f[4][4], a_lo_f[4][4];
#pragma unroll
            for (int mi = 0; mi < 4; mi++) {
                u32 row = (u32)(warp_m * 64 + mi * 16 + jlow * 8 + rq);
                u32 off = row * 64u + ((g ^ (row & 3u)) * 16u);
                ldsm4(a_hi_f[mi], ah + off);
                ldsm4(a_lo_f[mi], al + off);
            }
            u32 b_hi_f[4][2];
#pragma unroll
            for (int pi = 0; pi < 2; pi++) {
                u32 row = (u32)(warp_n * 32 + pi * 16 + jlow * 8 + rq);
                u32 off = row * 64u + ((g ^ (row & 3u)) * 16u);
                u32 t0[4];
                ldsm4(t0, wh + off);
                b_hi_f[2*pi][0] = t0[0]; b_hi_f[2*pi][1] = t0[2];
                b_hi_f[2*pi+1][0] = t0[1]; b_hi_f[2*pi+1][1] = t0[3];
            }
#pragma unroll
            for (int mi = 0; mi < 4; mi++)
#pragma unroll
                for (int ni = 0; ni < 4; ni++) {
                    mma16816(acc[mi][ni], a_hi_f[mi], b_hi_f[ni]);
                    mma16816(acc[mi][ni], a_lo_f[mi], b_hi_f[ni]);
                }
        }
        s_cur = (s_cur == 2) ? 0 : s_cur + 1;
        s_pre = (s_pre == 2) ? 0 : s_pre + 1;
    }

    // ---------------- epilogue ----------------
    const int qrow = lane >> 2, qcol = (lane & 3) * 2;
    const int n_warp0 = bn * 128 + warp_n * 32;

    if (ACT == 5) {
        // silu always; z<2 additionally l2norm per head-row.
#pragma unroll
        for (int mi = 0; mi < 4; mi++)
#pragma unroll
            for (int ni = 0; ni < 4; ni++)
#pragma unroll
                for (int e = 0; e < 4; e++) {
                    float x = acc[mi][ni][e];
                    acc[mi][ni][e] = x / (1.0f + expf(-x));
                }
        float* C = scratch_resolve(Cid + bz);
        if (bz < 2) {
            const float sscale = (bz == 0) ? 0.08838834764831845f : 1.0f;
            __syncthreads();                      // stage buffers reusable
            float* red = (float*)dsm;             // [128 rows][4 warp_n]
#pragma unroll
            for (int mi = 0; mi < 4; mi++)
#pragma unroll
                for (int half = 0; half < 2; half++) {
                    float ss = 0.f;
#pragma unroll
                    for (int ni = 0; ni < 4; ni++) {
                        float x0 = acc[mi][ni][half * 2];
                        float x1 = acc[mi][ni][half * 2 + 1];
                        ss += x0 * x0 + x1 * x1;
                    }
                    ss += __shfl_xor_sync(0xffffffffu, ss, 1);
                    ss += __shfl_xor_sync(0xffffffffu, ss, 2);
                    if ((lane & 3) == 0) {
                        int rowl = warp_m * 64 + mi * 16 + half * 8 + qrow;
                        red[rowl * 4 + warp_n] = ss;
                    }
                }
            __syncthreads();
#pragma unroll
            for (int mi = 0; mi < 4; mi++)
#pragma unroll
                for (int half = 0; half < 2; half++) {
                    int rowl = warp_m * 64 + mi * 16 + half * 8 + qrow;
                    float tot = red[rowl * 4] + red[rowl * 4 + 1]
                              + red[rowl * 4 + 2] + red[rowl * 4 + 3];
                    float r = rsqrtf(tot + 1e-6f) * sscale;
                    const int m = bm * 128 + rowl;
                    float* crow = C + (size_t)m * Ntot + n_warp0;
#pragma unroll
                    for (int ni = 0; ni < 4; ni++) {
                        float2 o2;
                        o2.x = acc[mi][ni][half * 2]     * r;
                        o2.y = acc[mi][ni][half * 2 + 1] * r;
                        *(float2*)(crow + ni * 8 + qcol) = o2;
                    }
                }
        } else {
#pragma unroll
            for (int mi = 0; mi < 4; mi++)
#pragma unroll
                for (int half = 0; half < 2; half++) {
                    const int m = bm * 128 + warp_m * 64 + mi * 16 + half * 8 + qrow;
                    float* crow = C + (size_t)m * Ntot + n_warp0;
#pragma unroll
                    for (int ni = 0; ni < 4; ni++) {
                        float2 o2;
                        o2.x = acc[mi][ni][half * 2];
                        o2.y = acc[mi][ni][half * 2 + 1];
                        *(float2*)(crow + ni * 8 + qcol) = o2;
                    }
                }
        }
        return;
    }

    float* C = (Cid >= 0) ? scratch_resolve(Cid) : Cext;
#pragma unroll
    for (int mi = 0; mi < 4; mi++) {
#pragma unroll
        for (int half = 0; half < 2; half++) {
            const int m = bm * 128 + warp_m * 64 + mi * 16 + half * 8 + qrow;
#pragma unroll
            for (int ni = 0; ni < 4; ni++) {
                float x0 = acc[mi][ni][half * 2];
                float x1 = acc[mi][ni][half * 2 + 1];
                const int n = n_warp0 + ni * 8 + qcol;
                if (ACT == 2) {
                    float a0 = expf(aux1[n >> 7]);
                    float a1 = expf(aux1[(n + 1) >> 7]);
                    float s0 = x0 + aux2[n], s1 = x1 + aux2[n + 1];
                    s0 = (s0 > 20.0f) ? s0 : log1pf(expf(s0));
                    s1 = (s1 > 20.0f) ? s1 : log1pf(expf(s1));
                    x0 = expf(-a0 * s0); x1 = expf(-a1 * s1);
                } else if (ACT == 3) {
                    x0 = 1.0f / (1.0f + expf(-(x0 + aux1[n])));
                    x1 = 1.0f / (1.0f + expf(-(x1 + aux1[n + 1])));
                }
                if (Cid == -2) {
                    __half h0 = __float2half_rn(x0), h1 = __float2half_rn(x1);
                    __half l0 = __float2half_rn(x0 - __half2float(h0));
                    __half l1 = __float2half_rn(x1 - __half2float(h1));
                    size_t base = (size_t)m * Ntot + n;
                    *(u32*)(g_hfpool + o_hi + base) =
                        (u32)__half_as_ushort(h0) | ((u32)__half_as_ushort(h1) << 16);
                    *(u32*)(g_hfpool + o_lo + base) =
                        (u32)__half_as_ushort(l0) | ((u32)__half_as_ushort(l1) << 16);
                } else {
                    float2 o2; o2.x = x0; o2.y = x1;
                    *(float2*)(C + (size_t)m * Ntot + n) = o2;
                }
            }
        }
    }
}

// --------------------------- beta = sigmoid(h @ b_w^T) ---------------------
__global__ __launch_bounds__(512) void beta_kernel(
    const float* __restrict__ H, const float* __restrict__ BW)
{
    float* BETA = scratch_resolve(ID_BETA);
    const int m = blockIdx.x;
    const int w = threadIdx.x >> 5, lane = threadIdx.x & 31;
    const float4* hr = (const float4*)(H + (size_t)m * HIDc);
    const float4* br = (const float4*)(BW + (size_t)w * HIDc);
    float s = 0.f;
#pragma unroll 4
    for (int i = lane; i < HIDc / 4; i += 32) {
        float4 a = hr[i], b = br[i];
        s += a.x * b.x + a.y * b.y + a.z * b.z + a.w * b.w;
    }
#pragma unroll
    for (int off = 16; off > 0; off >>= 1)
        s += __shfl_xor_sync(0xffffffffu, s, off);
    if (lane == 0) BETA[(size_t)m * Hc + w] = 1.0f / (1.0f + expf(-s));
}

// ---------- gated RMS norm: og = rms(o)*w*sigf, emitted as fp16 hi/lo ------
__global__ __launch_bounds__(128) void gate_kernel(const float* __restrict__ NW)
{
    const float* O    = scratch_resolve(ID_O);
    const float* SIGF = scratch_resolve(ID_SIGF);
    const int h = blockIdx.x, m = blockIdx.y;
    const int v = threadIdx.x;
    const size_t off = (size_t)m * HIDc + (size_t)h * DVc + v;
    float x = O[off];
    float s = x * x;
#pragma unroll
    for (int o = 16; o > 0; o >>= 1) s += __shfl_xor_sync(0xffffffffu, s, o);
    __shared__ float red[4];
    if ((v & 31) == 0) red[v >> 5] = s;
    __syncthreads();
    float tot = red[0] + red[1] + red[2] + red[3];
    float r = rsqrtf(tot * (1.0f / DVc) + 1e-5f);
    float y = x * r * NW[v] * SIGF[off];
    __half hi = __float2half_rn(y);
    __half lo = __float2half_rn(y - __half2float(hi));
    g_hfpool[OFF_OG_HI + off] = hi;
    g_hfpool[OFF_OG_LO + off] = lo;
}

// ------------------------------ recurrent scan -----------------------------
// grid (2, H, B); 256 threads. CTA owns 64 v-cols; 4 threads split the 128-k
// dim (kq = tid&3, 32 k each, 16 state pairs/thread). 4 smem stages, prefetch
// distance 2 -> single barrier per step. Rows skewed +4 floats per 32-block.
#define SROW 144
#define SKW(i) ((i) + ((((u32)(i)) >> 5) << 2))

__global__ __launch_bounds__(256) void scan_kernel(
    const float* __restrict__ S0,
    float* __restrict__ Sout, int writeS)
{
    const float* Q    = scratch_resolve(ID_Q);
    const float* K    = scratch_resolve(ID_K);
    const float* V    = scratch_resolve(ID_V);
    const float* EG   = scratch_resolve(ID_EG);
    const float* BETA = scratch_resolve(ID_BETA);
    float*       O    = scratch_resolve(ID_O);

    const int vh = blockIdx.x, h = blockIdx.y, b = blockIdx.z;
    const int tid = threadIdx.x;
    const int vloc = tid >> 2, kq = tid & 3;
    const int v = vh * 64 + vloc;
    const int ks = kq * 32;

    __shared__ float sbuf[4][4][SROW];   // [stage][k,q,v,eg][128 skewed]
    __shared__ float sbeta[4];

    const size_t rowbase = (size_t)b * Tc * HIDc + (size_t)h * DKc;

    ull S[16];
    {
        const float* s0p = S0 + (((size_t)(b * Hc + h) * DKc + ks) * DVc + v);
#pragma unroll
        for (int j2 = 0; j2 < 16; j2++)
            S[j2] = f2pack(s0p[(size_t)(2 * j2) * DVc], s0p[(size_t)(2 * j2 + 1) * DVc]);
    }

    const int grp = tid >> 6, idx = tid & 63;
    const float* srcs[4] = {K, Q, V, EG};

#pragma unroll
    for (int t = 0; t < 2; t++) {
        if (idx < 32)
            cp16(&sbuf[t][grp][idx * 4 + ((idx >> 3) << 2)],
                 srcs[grp] + rowbase + (size_t)t * HIDc + idx * 4);
        if (tid == 0) cp4(&sbeta[t], BETA + ((size_t)(b * Tc + t)) * Hc + h);
        cp_commit();
    }

    for (int t = 0; t < Tc; t++) {
        if (t + 2 < Tc) {
            const int st = (t + 2) & 3;
            if (idx < 32)
                cp16(&sbuf[st][grp][idx * 4 + ((idx >> 3) << 2)],
                     srcs[grp] + rowbase + (size_t)(t + 2) * HIDc + idx * 4);
            if (tid == 0) cp4(&sbeta[st], BETA + ((size_t)(b * Tc + t + 2)) * Hc + h);
            cp_commit();
            asm volatile("cp.async.wait_group 2;" ::: "memory");
        } else {
            asm volatile("cp.async.wait_group 0;" ::: "memory");
        }
        __syncthreads();

        const int cb = t & 3;
        const float beta = sbeta[cb];
        const float vv = sbuf[cb][2][SKW(v)];
        const int kb = ks + kq * 4;        // skewed base for this k-quarter

        ull k2[16];
        ull kva = 0ull, kvb = 0ull;
#pragma unroll
        for (int j2 = 0; j2 < 16; j2 += 2) {
            k2[j2]     = *(const ull*)&sbuf[cb][0][kb + 2 * j2];
            k2[j2 + 1] = *(const ull*)&sbuf[cb][0][kb + 2 * j2 + 2];
            ull e0 = *(const ull*)&sbuf[cb][3][kb + 2 * j2];
            ull e1 = *(const ull*)&sbuf[cb][3][kb + 2 * j2 + 2];
            S[j2]     = fmul2(S[j2],     e0);
            S[j2 + 1] = fmul2(S[j2 + 1], e1);
            kva = ffma2(k2[j2],     S[j2],     kva);
            kvb = ffma2(k2[j2 + 1], S[j2 + 1], kvb);
        }
        ull kv2 = fadd2(kva, kvb);
        float2 kvp = f2unpack(kv2);
        float kv = kvp.x + kvp.y;
        kv += __shfl_xor_sync(0xffffffffu, kv, 1);
        kv += __shfl_xor_sync(0xffffffffu, kv, 2);

        const float delta = (vv - kv) * beta;
        const ull d2 = f2pack(delta, delta);

        ull oa = 0ull, ob = 0ull;
#pragma unroll
        for (int j2 = 0; j2 < 16; j2 += 2) {
            S[j2]     = ffma2(k2[j2],     d2, S[j2]);
            S[j2 + 1] = ffma2(k2[j2 + 1], d2, S[j2 + 1]);
            ull q0 = *(const ull*)&sbuf[cb][1][kb + 2 * j2];
            ull q1 = *(const ull*)&sbuf[cb][1][kb + 2 * j2 + 2];
            oa = ffma2(q0, S[j2],     oa);
            ob = ffma2(q1, S[j2 + 1], ob);
        }
        ull o2 = fadd2(oa, ob);
        float2 op = f2unpack(o2);
        float o = op.x + op.y;
        o += __shfl_xor_sync(0xffffffffu, o, 1);
        o += __shfl_xor_sync(0xffffffffu, o, 2);
        if (kq == 0)
            O[rowbase + (size_t)t * HIDc + v] = o;
    }

    if (writeS) {
        float* sp = Sout + (((size_t)(b * Hc + h) * DKc + ks) * DVc + v);
#pragma unroll
        for (int j2 = 0; j2 < 16; j2++) {
            float2 c = f2unpack(S[j2]);
            sp[(size_t)(2 * j2) * DVc]     = c.x;
            sp[(size_t)(2 * j2 + 1) * DVc] = c.y;
        }
    }
}

// ------------------------------ host launcher ------------------------------
extern "C" void kernel_launch(void* const* d_in, const int* in_sizes, int n_in,
                              void* d_out, int out_size)
{
    const float* h      = (const float*)d_in[0];
    const float* S0     = (const float*)d_in[1];
    const float* q_w    = (const float*)d_in[2];
    const float* k_w    = (const float*)d_in[3];
    const float* v_w    = (const float*)d_in[4];
    const float* f_w0   = (const float*)d_in[5];
    const float* f_w1   = (const float*)d_in[6];
    const float* b_w    = (const float*)d_in[7];
    const float* A_log  = (const float*)d_in[8];
    const float* dt_b   = (const float*)d_in[9];
    const float* g_w0   = (const float*)d_in[10];
    const float* g_w1   = (const float*)d_in[11];
    const float* g_b1   = (const float*)d_in[12];
    const float* o_nw   = (const float*)d_in[13];
    const float* o_w    = (const float*)d_in[14];
    float* out = (float*)d_out;

    cudaFuncSetAttribute(mma_gemm<0>, cudaFuncAttributeMaxDynamicSharedMemorySize, GSMEM);
    cudaFuncSetAttribute(mma_gemm<2>, cudaFuncAttributeMaxDynamicSharedMemorySize, GSMEM);
    cudaFuncSetAttribute(mma_gemm<3>, cudaFuncAttributeMaxDynamicSharedMemorySize, GSMEM);
    cudaFuncSetAttribute(mma_gemm<5>, cudaFuncAttributeMaxDynamicSharedMemorySize, GSMEM);

    const dim3 g_big(HIDc / 128, Mc / 128);       // (16, 64)
    const dim3 g_qkv(HIDc / 128, Mc / 128, 3);    // (16, 64, 3)
    const dim3 g_n128(1, Mc / 128);               // (1, 64)

    // 1. merged split (h: hi+lo; weights: hi)
    split_all<<<CUM8, 256>>>(h, q_w, k_w, v_w, o_w, f_w0, g_w0, f_w1, g_w1);

    // 2. beta
    beta_kernel<<<Mc, 512>>>(h, b_w);

    // 3-4. skinny K=2048 -> N=128 GEMMs (direct fp16 hi/lo emit)
    mma_gemm<0><<<g_n128, 256, GSMEM>>>(OFF_HB_HI, OFF_HB_LO, OFF_FW0_HI,
                                        nullptr, -2, 128, HIDc, nullptr, nullptr,
                                        OFF_TMP_HI, OFF_TMP_LO);
    mma_gemm<0><<<g_n128, 256, GSMEM>>>(OFF_HB_HI, OFF_HB_LO, OFF_GW0_HI,
                                        nullptr, -2, 128, HIDc, nullptr, nullptr,
                                        OFF_TMP2_HI, OFF_TMP2_LO);

    // 5. eg = exp(-exp(A_log)*softplus(tmp@f_w1^T + dt_bias))
    mma_gemm<2><<<g_big, 256, GSMEM>>>(OFF_TMP_HI, OFF_TMP_LO, OFF_FW1_HI,
                                       nullptr, ID_EG, HIDc, 128, A_log, dt_b,
                                       0, 0);

    // 6. merged q/k/v projections (z selects weight + epilogue) — ncu target
    mma_gemm<5><<<g_qkv, 256, GSMEM>>>(OFF_HB_HI, OFF_HB_LO, OFF_WQ_HI,
                                       nullptr, ID_Q, HIDc, HIDc, nullptr, nullptr,
                                       0, 0);

    // 7. sigf = sigmoid(tmp2@g_w1^T + g_b1)
    mma_gemm<3><<<g_big, 256, GSMEM>>>(OFF_TMP2_HI, OFF_TMP2_LO, OFF_GW1_HI,
                                       nullptr, ID_SIGF, HIDc, 128, g_b1, nullptr,
                                       0, 0);

    // 8. recurrent scan
    const size_t out_elems = (size_t)Mc * HIDc;                 // 16,777,216
    const size_t s_elems   = (size_t)Bc * Hc * DKc * DVc;       //  1,048,576
    const int writeS = ((size_t)out_size >= out_elems + s_elems) ? 1 : 0;
    scan_kernel<<<dim3(2, Hc, Bc), 256>>>(S0, out + out_elems, writeS);

    // 9-10. gated rms norm (emits fp16 hi/lo) + final projection
    gate_kernel<<<dim3(Hc, Mc), 128>>>(o_nw);
    mma_gemm<0><<<g_big, 256, GSMEM>>>(OFF_OG_HI, OFF_OG_LO, OFF_WO_HI,
                                       out, -1, HIDc, HIDc, nullptr, nullptr,
                                       0, 0);
}